// round 2
// baseline (speedup 1.0000x reference)
#include <cuda_runtime.h>
#include <math.h>

#define DD 300
#define NCOLS 1800
#define KK 304
#define MAXN 50000
#define MAXE 250000

// ---- static scratch (allocation-free rule: __device__ globals) ----
__device__ float d_Apad[MAXN * KK];          // [N][304] = [x | normals | 1]
__device__ float d_Wbig[KK * NCOLS];         // [304][1800]
__device__ float d_S[MAXN * NCOLS];          // [N][1800] = Q|K|V|skip|Cd|Cs
__device__ float d_w8[MAXE * 8];             // prob(5), t0, t1
__device__ float d_e4[MAXE * 4];             // exp(alpha) per head
__device__ float d_den[MAXN * 4];            // softmax denominators
__device__ float d_NLi[3 * DD];
__device__ float d_NLj[3 * DD];
__device__ float d_W2f[2 * DD];
__device__ float d_c0[DD];
__device__ float d_T8[8 * DD];
__device__ float d_G8[8 * DD];

// ---------------- fold 1: small matrix foldings ----------------
__global__ void fold1_kernel(const float* __restrict__ Wn, const float* __restrict__ Wxy,
                             const float* __restrict__ Wloc, const float* __restrict__ Wfus,
                             const float* __restrict__ vocab, const float* __restrict__ bxy,
                             const float* __restrict__ bn, const float* __restrict__ bobj,
                             const float* __restrict__ bloc, const float* __restrict__ bfus) {
    int c = blockIdx.x * blockDim.x + threadIdx.x;
    if (c >= DD) return;
    float nli0 = 0, nli1 = 0, nli2 = 0, nlj0 = 0, nlj1 = 0, nlj2 = 0;
    float w20 = 0, w21 = 0, c0 = 0;
    float t0 = 0, t1 = 0, t2 = 0, t3 = 0, t4 = 0, t5 = 0, t6 = 0;
    for (int k = 0; k < DD; k++) {
        float wl0 = Wloc[k * DD + c];              // xy rows
        float wl1 = Wloc[(DD + k) * DD + c];       // ni rows
        float wl2 = Wloc[(2 * DD + k) * DD + c];   // nj rows
        float wn0 = Wn[k], wn1 = Wn[DD + k], wn2 = Wn[2 * DD + k];
        nli0 = fmaf(wn0, wl1, nli0); nli1 = fmaf(wn1, wl1, nli1); nli2 = fmaf(wn2, wl1, nli2);
        nlj0 = fmaf(wn0, wl2, nlj0); nlj1 = fmaf(wn1, wl2, nlj1); nlj2 = fmaf(wn2, wl2, nlj2);
        w20 = fmaf(Wxy[k], wl0, w20); w21 = fmaf(Wxy[DD + k], wl0, w21);
        c0 = fmaf(bxy[k], wl0, c0);
        c0 = fmaf(bn[k], wl1 + wl2, c0);
        float wf0 = Wfus[k * DD + c];              // vert rows
        float wf1 = Wfus[(DD + k) * DD + c];       // horiz rows
        t0 = fmaf(vocab[2 * DD + k], wf1, t0);
        t1 = fmaf(vocab[3 * DD + k], wf1, t1);
        t2 = fmaf(vocab[4 * DD + k], wf1, t2);
        t3 = fmaf(vocab[5 * DD + k], wf1, t3);
        t4 = fmaf(vocab[6 * DD + k], wf1, t4);
        t5 = fmaf(vocab[k], wf0, t5);
        t6 = fmaf(vocab[DD + k], wf0, t6);
    }
    d_NLi[0 * DD + c] = nli0; d_NLi[1 * DD + c] = nli1; d_NLi[2 * DD + c] = nli2;
    d_NLj[0 * DD + c] = nlj0; d_NLj[1 * DD + c] = nlj1; d_NLj[2 * DD + c] = nlj2;
    d_W2f[c] = w20; d_W2f[DD + c] = w21;
    d_c0[c] = c0 + bobj[c] + bloc[c];
    d_T8[0 * DD + c] = t0; d_T8[1 * DD + c] = t1; d_T8[2 * DD + c] = t2;
    d_T8[3 * DD + c] = t3; d_T8[4 * DD + c] = t4; d_T8[5 * DD + c] = t5;
    d_T8[6 * DD + c] = t6; d_T8[7 * DD + c] = bfus[c];
}

// ---------------- fold 2: G8 = T8 @ We ----------------
__global__ void fold2_kernel(const float* __restrict__ We) {
    int c = blockIdx.x * blockDim.x + threadIdx.x;
    if (c >= DD) return;
    float g[8] = {0, 0, 0, 0, 0, 0, 0, 0};
    for (int k = 0; k < DD; k++) {
        float w = We[k * DD + c];
        #pragma unroll
        for (int j = 0; j < 8; j++) g[j] = fmaf(d_T8[j * DD + k], w, g[j]);
    }
    #pragma unroll
    for (int j = 0; j < 8; j++) d_G8[j * DD + c] = g[j];
}

// ---------------- build A (padded) ----------------
__global__ void buildA_kernel(const float* __restrict__ x, const float* __restrict__ nrm, int Nn) {
    int idx = blockIdx.x * blockDim.x + threadIdx.x;
    if (idx >= Nn * KK) return;
    int n = idx / KK, k = idx - n * KK;
    float v;
    if (k < DD) v = x[n * DD + k];
    else if (k < DD + 3) v = nrm[n * 3 + (k - DD)];
    else v = 1.0f;
    d_Apad[idx] = v;
}

// ---------------- build Wbig ----------------
__global__ void buildW_kernel(const float* __restrict__ Wq, const float* __restrict__ Wk,
                              const float* __restrict__ Wv, const float* __restrict__ Wskip,
                              const float* __restrict__ Wobj, const float* __restrict__ bq,
                              const float* __restrict__ bk, const float* __restrict__ bv,
                              const float* __restrict__ bskip) {
    int idx = blockIdx.x * blockDim.x + threadIdx.x;
    if (idx >= KK * NCOLS) return;
    int k = idx / NCOLS, c = idx - k * NCOLS;
    int b = c / DD, cc = c - b * DD;
    float v = 0.0f;
    if (k < DD) {
        if (b == 0) v = Wq[k * DD + cc];
        else if (b == 1) v = Wk[k * DD + cc];
        else if (b == 2) v = Wv[k * DD + cc];
        else if (b == 3) v = Wskip[k * DD + cc];
        else if (b == 4) v = Wobj[k * DD + cc] - Wobj[(DD + k) * DD + cc];
        else v = Wobj[(DD + k) * DD + cc];
    } else if (k < DD + 3) {
        int r = k - DD;
        if (b == 4) v = d_NLi[r * DD + cc];
        else if (b == 5) v = d_NLj[r * DD + cc];
    } else {
        if (b == 0) v = bq[cc];
        else if (b == 1) v = bk[cc];
        else if (b == 2) v = bv[cc];
        else if (b == 3) v = bskip[cc];
        else if (b == 4) v = d_c0[cc];
    }
    d_Wbig[idx] = v;
}

// ---------------- node GEMM: S = Apad @ Wbig  (M x 304 @ 304 x 1800) ----------------
__global__ void __launch_bounds__(256) gemm_kernel(int M) {
    __shared__ float As[2][16][128];
    __shared__ float Bs[2][16][128];
    int tid = threadIdx.x;
    int tx = tid & 15, ty = tid >> 4;
    int row0 = blockIdx.y * 128, col0 = blockIdx.x * 128;
    float acc[8][8];
    #pragma unroll
    for (int i = 0; i < 8; i++)
        #pragma unroll
        for (int j = 0; j < 8; j++) acc[i][j] = 0.0f;

    const int NK = KK / 16;  // 19

    // prologue load step 0 into buf 0
    {
        #pragma unroll
        for (int u = 0; u < 2; u++) {
            int idx = tid + u * 256;
            int r = idx >> 2;
            int cv = (idx & 3) * 4;
            int grow = row0 + r;
            float4 val = make_float4(0.f, 0.f, 0.f, 0.f);
            if (grow < M) val = *(const float4*)&d_Apad[grow * KK + cv];
            As[0][cv + 0][r] = val.x; As[0][cv + 1][r] = val.y;
            As[0][cv + 2][r] = val.z; As[0][cv + 3][r] = val.w;
        }
        #pragma unroll
        for (int u = 0; u < 2; u++) {
            int idx = tid + u * 256;
            int r = idx >> 5;
            int cv = (idx & 31) * 4;
            int gcol = col0 + cv;
            float4 val = make_float4(0.f, 0.f, 0.f, 0.f);
            if (gcol < NCOLS) val = *(const float4*)&d_Wbig[r * NCOLS + gcol];
            *(float4*)&Bs[0][r][cv] = val;
        }
    }
    __syncthreads();

    for (int s = 0; s < NK; s++) {
        int cbuf = s & 1, nbuf = cbuf ^ 1;
        if (s + 1 < NK) {
            int kt = (s + 1) * 16;
            #pragma unroll
            for (int u = 0; u < 2; u++) {
                int idx = tid + u * 256;
                int r = idx >> 2;
                int cv = (idx & 3) * 4;
                int grow = row0 + r;
                float4 val = make_float4(0.f, 0.f, 0.f, 0.f);
                if (grow < M) val = *(const float4*)&d_Apad[grow * KK + kt + cv];
                As[nbuf][cv + 0][r] = val.x; As[nbuf][cv + 1][r] = val.y;
                As[nbuf][cv + 2][r] = val.z; As[nbuf][cv + 3][r] = val.w;
            }
            #pragma unroll
            for (int u = 0; u < 2; u++) {
                int idx = tid + u * 256;
                int r = idx >> 5;
                int cv = (idx & 31) * 4;
                int gcol = col0 + cv;
                float4 val = make_float4(0.f, 0.f, 0.f, 0.f);
                if (gcol < NCOLS) val = *(const float4*)&d_Wbig[(kt + r) * NCOLS + gcol];
                *(float4*)&Bs[nbuf][r][cv] = val;
            }
        }
        #pragma unroll
        for (int k = 0; k < 16; k++) {
            float4 a0 = *(float4*)&As[cbuf][k][ty * 8];
            float4 a1 = *(float4*)&As[cbuf][k][ty * 8 + 4];
            float4 b0 = *(float4*)&Bs[cbuf][k][tx * 8];
            float4 b1 = *(float4*)&Bs[cbuf][k][tx * 8 + 4];
            float av[8] = {a0.x, a0.y, a0.z, a0.w, a1.x, a1.y, a1.z, a1.w};
            float bv[8] = {b0.x, b0.y, b0.z, b0.w, b1.x, b1.y, b1.z, b1.w};
            #pragma unroll
            for (int i = 0; i < 8; i++)
                #pragma unroll
                for (int j = 0; j < 8; j++) acc[i][j] = fmaf(av[i], bv[j], acc[i][j]);
        }
        __syncthreads();
    }

    #pragma unroll
    for (int i = 0; i < 8; i++) {
        int gr = row0 + ty * 8 + i;
        if (gr >= M) continue;
        #pragma unroll
        for (int jv = 0; jv < 8; jv += 4) {
            int gc = col0 + tx * 8 + jv;
            if (gc < NCOLS) {
                float4 v = make_float4(acc[i][jv], acc[i][jv + 1], acc[i][jv + 2], acc[i][jv + 3]);
                *(float4*)&d_S[gr * NCOLS + gc] = v;
            }
        }
    }
}

// ---------------- copy skip block into d_out ----------------
__global__ void skipcopy_kernel(float* __restrict__ out, int Nn) {
    int idx = blockIdx.x * blockDim.x + threadIdx.x;
    if (idx >= Nn * DD) return;
    int n = idx / DD, c = idx - n * DD;
    out[idx] = d_S[n * NCOLS + 900 + c];
}

__global__ void zeroden_kernel(int Nn) {
    int idx = blockIdx.x * blockDim.x + threadIdx.x;
    if (idx < Nn * 4) d_den[idx] = 0.0f;
}

// ---------------- edge pass B ----------------
__global__ void __launch_bounds__(256) edgeB_kernel(const int* __restrict__ EI,
                                                    const float* __restrict__ EA,
                                                    const float* __restrict__ Wcls,
                                                    const float* __restrict__ bcls, int Ee) {
    __shared__ float sWcls[DD * 5];
    __shared__ float sG[8 * DD];
    __shared__ float sW2[2 * DD];
    __shared__ float sBcls[5];
    for (int i = threadIdx.x; i < DD * 5; i += 256) sWcls[i] = Wcls[i];
    for (int i = threadIdx.x; i < 8 * DD; i += 256) sG[i] = d_G8[i];
    for (int i = threadIdx.x; i < 2 * DD; i += 256) sW2[i] = d_W2f[i];
    if (threadIdx.x < 5) sBcls[threadIdx.x] = bcls[threadIdx.x];
    __syncthreads();

    int lane = threadIdx.x & 31;
    int warp = (blockIdx.x * 256 + threadIdx.x) >> 5;
    int nw = (gridDim.x * 256) >> 5;

    for (int e = warp; e < Ee; e += nw) {
        int src = EI[e], dst = EI[Ee + e];
        float ea0 = EA[4 * e + 0], ea1 = EA[4 * e + 1];
        float ea2 = EA[4 * e + 2], ea3 = EA[4 * e + 3];
        const float* rowD = d_S + dst * NCOLS;
        const float* rowS = d_S + src * NCOLS;

        float l0 = 0, l1 = 0, l2 = 0, l3 = 0, l4 = 0;
        for (int c = lane; c < DD; c += 32) {
            float z = rowD[1200 + c] + rowS[1500 + c] + ea2 * sW2[c] + ea3 * sW2[DD + c];
            float h = tanhf(z);
            const float* wc = sWcls + c * 5;
            l0 = fmaf(h, wc[0], l0); l1 = fmaf(h, wc[1], l1); l2 = fmaf(h, wc[2], l2);
            l3 = fmaf(h, wc[3], l3); l4 = fmaf(h, wc[4], l4);
        }
        #pragma unroll
        for (int o = 16; o; o >>= 1) {
            l0 += __shfl_xor_sync(0xffffffffu, l0, o);
            l1 += __shfl_xor_sync(0xffffffffu, l1, o);
            l2 += __shfl_xor_sync(0xffffffffu, l2, o);
            l3 += __shfl_xor_sync(0xffffffffu, l3, o);
            l4 += __shfl_xor_sync(0xffffffffu, l4, o);
        }
        l0 += sBcls[0]; l1 += sBcls[1]; l2 += sBcls[2]; l3 += sBcls[3]; l4 += sBcls[4];
        float m = fmaxf(fmaxf(fmaxf(l0, l1), fmaxf(l2, l3)), l4);
        float p0 = __expf(l0 - m), p1 = __expf(l1 - m), p2 = __expf(l2 - m);
        float p3 = __expf(l3 - m), p4 = __expf(l4 - m);
        float inv = 1.0f / (p0 + p1 + p2 + p3 + p4);
        p0 *= inv; p1 *= inv; p2 *= inv; p3 *= inv; p4 *= inv;
        float t0 = ea0 > 0.0f ? 1.0f : 0.0f;
        float t1 = ea1 < 0.0f ? 1.0f : 0.0f;
        if (lane == 0) {
            float* w = d_w8 + e * 8;
            w[0] = p0; w[1] = p1; w[2] = p2; w[3] = p3; w[4] = p4; w[5] = t0; w[6] = t1;
        }

        float a0 = 0, a1 = 0, a2 = 0, a3 = 0;
        for (int c = lane; c < DD; c += 32) {
            float ef = sG[2100 + c];
            ef = fmaf(p0, sG[c], ef);
            ef = fmaf(p1, sG[300 + c], ef);
            ef = fmaf(p2, sG[600 + c], ef);
            ef = fmaf(p3, sG[900 + c], ef);
            ef = fmaf(p4, sG[1200 + c], ef);
            ef = fmaf(t0, sG[1500 + c], ef);
            ef = fmaf(t1, sG[1800 + c], ef);
            float pr = rowD[c] * (rowS[300 + c] + ef);
            if (c < 75) a0 += pr;
            else if (c < 150) a1 += pr;
            else if (c < 225) a2 += pr;
            else a3 += pr;
        }
        #pragma unroll
        for (int o = 16; o; o >>= 1) {
            a0 += __shfl_xor_sync(0xffffffffu, a0, o);
            a1 += __shfl_xor_sync(0xffffffffu, a1, o);
            a2 += __shfl_xor_sync(0xffffffffu, a2, o);
            a3 += __shfl_xor_sync(0xffffffffu, a3, o);
        }
        const float sc = 0.115470053837925152f;  // 1/sqrt(75)
        float e0 = __expf(a0 * sc), e1 = __expf(a1 * sc);
        float e2 = __expf(a2 * sc), e3 = __expf(a3 * sc);
        if (lane == 0) {
            float* ep = d_e4 + e * 4;
            ep[0] = e0; ep[1] = e1; ep[2] = e2; ep[3] = e3;
            atomicAdd(&d_den[dst * 4 + 0], e0);
            atomicAdd(&d_den[dst * 4 + 1], e1);
            atomicAdd(&d_den[dst * 4 + 2], e2);
            atomicAdd(&d_den[dst * 4 + 3], e3);
        }
    }
}

// ---------------- edge pass C ----------------
__global__ void __launch_bounds__(256) edgeC_kernel(const int* __restrict__ EI,
                                                    float* __restrict__ out, int Ee) {
    __shared__ float sG[8 * DD];
    for (int i = threadIdx.x; i < 8 * DD; i += 256) sG[i] = d_G8[i];
    __syncthreads();

    int lane = threadIdx.x & 31;
    int warp = (blockIdx.x * 256 + threadIdx.x) >> 5;
    int nw = (gridDim.x * 256) >> 5;

    for (int e = warp; e < Ee; e += nw) {
        int src = EI[e], dst = EI[Ee + e];
        const float* w = d_w8 + e * 8;
        float p0 = w[0], p1 = w[1], p2 = w[2], p3 = w[3], p4 = w[4], t0 = w[5], t1 = w[6];
        const float* ep = d_e4 + e * 4;
        float al0 = ep[0] / d_den[dst * 4 + 0];
        float al1 = ep[1] / d_den[dst * 4 + 1];
        float al2 = ep[2] / d_den[dst * 4 + 2];
        float al3 = ep[3] / d_den[dst * 4 + 3];
        const float* rowV = d_S + src * NCOLS + 600;
        float* orow = out + dst * DD;
        for (int c = lane; c < DD; c += 32) {
            float ef = sG[2100 + c];
            ef = fmaf(p0, sG[c], ef);
            ef = fmaf(p1, sG[300 + c], ef);
            ef = fmaf(p2, sG[600 + c], ef);
            ef = fmaf(p3, sG[900 + c], ef);
            ef = fmaf(p4, sG[1200 + c], ef);
            ef = fmaf(t0, sG[1500 + c], ef);
            ef = fmaf(t1, sG[1800 + c], ef);
            float v = rowV[c] + ef;
            float al = c < 75 ? al0 : (c < 150 ? al1 : (c < 225 ? al2 : al3));
            atomicAdd(&orow[c], v * al);
        }
    }
}

// ---------------- host launcher ----------------
extern "C" void kernel_launch(void* const* d_in, const int* in_sizes, int n_in,
                              void* d_out, int out_size) {
    const float* x     = (const float*)d_in[0];
    const int*   EI    = (const int*)d_in[1];
    const float* EA    = (const float*)d_in[2];
    const float* nrm   = (const float*)d_in[3];
    const float* Wq    = (const float*)d_in[4];
    const float* bq    = (const float*)d_in[5];
    const float* Wk    = (const float*)d_in[6];
    const float* bk    = (const float*)d_in[7];
    const float* Wv    = (const float*)d_in[8];
    const float* bv    = (const float*)d_in[9];
    const float* We    = (const float*)d_in[10];
    const float* Wn    = (const float*)d_in[11];
    const float* bn    = (const float*)d_in[12];
    const float* Wxy   = (const float*)d_in[13];
    const float* bxy   = (const float*)d_in[14];
    const float* Wloc  = (const float*)d_in[15];
    const float* bloc  = (const float*)d_in[16];
    const float* Wobj  = (const float*)d_in[17];
    const float* bobj  = (const float*)d_in[18];
    const float* Wfus  = (const float*)d_in[19];
    const float* bfus  = (const float*)d_in[20];
    const float* Wcls  = (const float*)d_in[21];
    const float* bcls  = (const float*)d_in[22];
    const float* Wskip = (const float*)d_in[23];
    const float* bskip = (const float*)d_in[24];
    const float* vocab = (const float*)d_in[25];

    int Nn = in_sizes[0] / DD;
    int Ee = in_sizes[1] / 2;
    float* out = (float*)d_out;

    fold1_kernel<<<(DD + 127) / 128, 128>>>(Wn, Wxy, Wloc, Wfus, vocab, bxy, bn, bobj, bloc, bfus);
    fold2_kernel<<<(DD + 127) / 128, 128>>>(We);
    buildA_kernel<<<(Nn * KK + 255) / 256, 256>>>(x, nrm, Nn);
    buildW_kernel<<<(KK * NCOLS + 255) / 256, 256>>>(Wq, Wk, Wv, Wskip, Wobj, bq, bk, bv, bskip);

    dim3 gg((NCOLS + 127) / 128, (Nn + 127) / 128);
    gemm_kernel<<<gg, 256>>>(Nn);

    skipcopy_kernel<<<(Nn * DD + 255) / 256, 256>>>(out, Nn);
    zeroden_kernel<<<(Nn * 4 + 255) / 256, 256>>>(Nn);

    edgeB_kernel<<<2048, 256>>>(EI, EA, Wcls, bcls, Ee);
    edgeC_kernel<<<2048, 256>>>(EI, out, Ee);
}

// round 3
// speedup vs baseline: 1.1502x; 1.1502x over previous
#include <cuda_runtime.h>
#include <mma.h>
#include <math.h>

using namespace nvcuda;

#define DD 300
#define NCOLS 1800
#define KK 304
#define MAXN 50000
#define MAXE 250000
#define MPAD 50048          // 391 * 128
#define SST  1920           // padded row stride of d_S (>= 15*128)

// ---- static scratch (allocation-free rule: __device__ globals) ----
__device__ float d_Apad[MAXN * KK];          // [N][304] = [x | normals | 1]
__device__ float d_Wbig[KK * NCOLS];         // [304][1800]
__device__ float d_S[(size_t)MPAD * SST];    // [N][1920] = Q|K|V|skip|Cd|Cs|pad
__device__ float d_w8[MAXE * 8];             // prob(5), t0, t1
__device__ float d_e4[MAXE * 4];             // exp(alpha) per head
__device__ float d_den[MAXN * 4];            // softmax denominators
__device__ float d_NLi[3 * DD];
__device__ float d_NLj[3 * DD];
__device__ float d_W2f[2 * DD];
__device__ float d_c0[DD];
__device__ float d_T8[8 * DD];
__device__ float d_G8[8 * DD];

__device__ __forceinline__ float fast_tanh(float x) {
    float r;
    asm("tanh.approx.f32 %0, %1;" : "=f"(r) : "f"(x));
    return r;
}

// ---------------- fold 1: small matrix foldings ----------------
__global__ void fold1_kernel(const float* __restrict__ Wn, const float* __restrict__ Wxy,
                             const float* __restrict__ Wloc, const float* __restrict__ Wfus,
                             const float* __restrict__ vocab, const float* __restrict__ bxy,
                             const float* __restrict__ bn, const float* __restrict__ bobj,
                             const float* __restrict__ bloc, const float* __restrict__ bfus) {
    int c = blockIdx.x * blockDim.x + threadIdx.x;
    if (c >= DD) return;
    float nli0 = 0, nli1 = 0, nli2 = 0, nlj0 = 0, nlj1 = 0, nlj2 = 0;
    float w20 = 0, w21 = 0, c0 = 0;
    float t0 = 0, t1 = 0, t2 = 0, t3 = 0, t4 = 0, t5 = 0, t6 = 0;
    for (int k = 0; k < DD; k++) {
        float wl0 = Wloc[k * DD + c];
        float wl1 = Wloc[(DD + k) * DD + c];
        float wl2 = Wloc[(2 * DD + k) * DD + c];
        float wn0 = Wn[k], wn1 = Wn[DD + k], wn2 = Wn[2 * DD + k];
        nli0 = fmaf(wn0, wl1, nli0); nli1 = fmaf(wn1, wl1, nli1); nli2 = fmaf(wn2, wl1, nli2);
        nlj0 = fmaf(wn0, wl2, nlj0); nlj1 = fmaf(wn1, wl2, nlj1); nlj2 = fmaf(wn2, wl2, nlj2);
        w20 = fmaf(Wxy[k], wl0, w20); w21 = fmaf(Wxy[DD + k], wl0, w21);
        c0 = fmaf(bxy[k], wl0, c0);
        c0 = fmaf(bn[k], wl1 + wl2, c0);
        float wf0 = Wfus[k * DD + c];
        float wf1 = Wfus[(DD + k) * DD + c];
        t0 = fmaf(vocab[2 * DD + k], wf1, t0);
        t1 = fmaf(vocab[3 * DD + k], wf1, t1);
        t2 = fmaf(vocab[4 * DD + k], wf1, t2);
        t3 = fmaf(vocab[5 * DD + k], wf1, t3);
        t4 = fmaf(vocab[6 * DD + k], wf1, t4);
        t5 = fmaf(vocab[k], wf0, t5);
        t6 = fmaf(vocab[DD + k], wf0, t6);
    }
    d_NLi[0 * DD + c] = nli0; d_NLi[1 * DD + c] = nli1; d_NLi[2 * DD + c] = nli2;
    d_NLj[0 * DD + c] = nlj0; d_NLj[1 * DD + c] = nlj1; d_NLj[2 * DD + c] = nlj2;
    d_W2f[c] = w20; d_W2f[DD + c] = w21;
    d_c0[c] = c0 + bobj[c] + bloc[c];
    d_T8[0 * DD + c] = t0; d_T8[1 * DD + c] = t1; d_T8[2 * DD + c] = t2;
    d_T8[3 * DD + c] = t3; d_T8[4 * DD + c] = t4; d_T8[5 * DD + c] = t5;
    d_T8[6 * DD + c] = t6; d_T8[7 * DD + c] = bfus[c];
}

// ---------------- fold 2: G8 = T8 @ We ----------------
__global__ void fold2_kernel(const float* __restrict__ We) {
    int c = blockIdx.x * blockDim.x + threadIdx.x;
    if (c >= DD) return;
    float g[8] = {0, 0, 0, 0, 0, 0, 0, 0};
    for (int k = 0; k < DD; k++) {
        float w = We[k * DD + c];
        #pragma unroll
        for (int j = 0; j < 8; j++) g[j] = fmaf(d_T8[j * DD + k], w, g[j]);
    }
    #pragma unroll
    for (int j = 0; j < 8; j++) d_G8[j * DD + c] = g[j];
}

// ---------------- build A (padded) ----------------
__global__ void buildA_kernel(const float* __restrict__ x, const float* __restrict__ nrm, int Nn) {
    int idx = blockIdx.x * blockDim.x + threadIdx.x;
    if (idx >= Nn * KK) return;
    int n = idx / KK, k = idx - n * KK;
    float v;
    if (k < DD) v = x[n * DD + k];
    else if (k < DD + 3) v = nrm[n * 3 + (k - DD)];
    else v = 1.0f;
    d_Apad[idx] = v;
}

// ---------------- build Wbig ----------------
__global__ void buildW_kernel(const float* __restrict__ Wq, const float* __restrict__ Wk,
                              const float* __restrict__ Wv, const float* __restrict__ Wskip,
                              const float* __restrict__ Wobj, const float* __restrict__ bq,
                              const float* __restrict__ bk, const float* __restrict__ bv,
                              const float* __restrict__ bskip) {
    int idx = blockIdx.x * blockDim.x + threadIdx.x;
    if (idx >= KK * NCOLS) return;
    int k = idx / NCOLS, c = idx - k * NCOLS;
    int b = c / DD, cc = c - b * DD;
    float v = 0.0f;
    if (k < DD) {
        if (b == 0) v = Wq[k * DD + cc];
        else if (b == 1) v = Wk[k * DD + cc];
        else if (b == 2) v = Wv[k * DD + cc];
        else if (b == 3) v = Wskip[k * DD + cc];
        else if (b == 4) v = Wobj[k * DD + cc] - Wobj[(DD + k) * DD + cc];
        else v = Wobj[(DD + k) * DD + cc];
    } else if (k < DD + 3) {
        int r = k - DD;
        if (b == 4) v = d_NLi[r * DD + cc];
        else if (b == 5) v = d_NLj[r * DD + cc];
    } else {
        if (b == 0) v = bq[cc];
        else if (b == 1) v = bk[cc];
        else if (b == 2) v = bv[cc];
        else if (b == 3) v = bskip[cc];
        else if (b == 4) v = d_c0[cc];
    }
    d_Wbig[idx] = v;
}

// ---------------- node GEMM (tf32 tensor cores): S = Apad @ Wbig ----------------
// M x 304 @ 304 x 1800, block tile 128x128, warp tile 64x32, wmma m16n16k8 tf32.
__global__ void __launch_bounds__(256) gemm_tf32_kernel(int M) {
    __shared__ __align__(32) float As[2][128][20];   // [row][k], ldm 20
    __shared__ __align__(32) float Bs[2][16][136];   // [k][col], ldm 136

    int tid = threadIdx.x;
    int wid = tid >> 5;
    int wm = wid >> 2;            // 0..1 -> row offset wm*64
    int wn = wid & 3;             // 0..3 -> col offset wn*32
    int row0 = blockIdx.y * 128, col0 = blockIdx.x * 128;

    wmma::fragment<wmma::accumulator, 16, 16, 8, float> acc[4][2];
    #pragma unroll
    for (int i = 0; i < 4; i++)
        #pragma unroll
        for (int j = 0; j < 2; j++) wmma::fill_fragment(acc[i][j], 0.0f);

    // A loader: thread -> (row = tid>>1, kv = (tid&1)*8), loads 8 k-values
    int ar = tid >> 1;
    int akv = (tid & 1) * 8;
    int agrow = row0 + ar;
    // B loader: thread -> (row = tid>>4, col = (tid&15)*8)
    int br = tid >> 4;
    int bc = (tid & 15) * 8;

    auto loadA = [&](int buf, int kt) {
        float4 v0 = make_float4(0.f, 0.f, 0.f, 0.f), v1 = v0;
        if (agrow < M) {
            v0 = *(const float4*)&d_Apad[agrow * KK + kt + akv];
            v1 = *(const float4*)&d_Apad[agrow * KK + kt + akv + 4];
        }
        v0.x = wmma::__float_to_tf32(v0.x); v0.y = wmma::__float_to_tf32(v0.y);
        v0.z = wmma::__float_to_tf32(v0.z); v0.w = wmma::__float_to_tf32(v0.w);
        v1.x = wmma::__float_to_tf32(v1.x); v1.y = wmma::__float_to_tf32(v1.y);
        v1.z = wmma::__float_to_tf32(v1.z); v1.w = wmma::__float_to_tf32(v1.w);
        *(float4*)&As[buf][ar][akv] = v0;
        *(float4*)&As[buf][ar][akv + 4] = v1;
    };
    auto loadB = [&](int buf, int kt) {
        int gcol = col0 + bc;
        const float* src = &d_Wbig[(kt + br) * NCOLS + gcol];
        float4 v0 = make_float4(0.f, 0.f, 0.f, 0.f), v1 = v0;
        if (gcol + 4 <= NCOLS) v0 = *(const float4*)src;
        if (gcol + 8 <= NCOLS) v1 = *(const float4*)(src + 4);
        v0.x = wmma::__float_to_tf32(v0.x); v0.y = wmma::__float_to_tf32(v0.y);
        v0.z = wmma::__float_to_tf32(v0.z); v0.w = wmma::__float_to_tf32(v0.w);
        v1.x = wmma::__float_to_tf32(v1.x); v1.y = wmma::__float_to_tf32(v1.y);
        v1.z = wmma::__float_to_tf32(v1.z); v1.w = wmma::__float_to_tf32(v1.w);
        *(float4*)&Bs[buf][br][bc] = v0;
        *(float4*)&Bs[buf][br][bc + 4] = v1;
    };

    loadA(0, 0);
    loadB(0, 0);
    __syncthreads();

    const int NT = KK / 16;  // 19
    for (int s = 0; s < NT; s++) {
        int cur = s & 1;
        if (s + 1 < NT) {
            loadA(cur ^ 1, (s + 1) * 16);
            loadB(cur ^ 1, (s + 1) * 16);
        }
        #pragma unroll
        for (int ks = 0; ks < 2; ks++) {
            int k0 = ks * 8;
            wmma::fragment<wmma::matrix_a, 16, 16, 8, wmma::precision::tf32, wmma::row_major> af[4];
            wmma::fragment<wmma::matrix_b, 16, 16, 8, wmma::precision::tf32, wmma::row_major> bf[2];
            #pragma unroll
            for (int i = 0; i < 4; i++)
                wmma::load_matrix_sync(af[i], &As[cur][wm * 64 + i * 16][k0], 20);
            #pragma unroll
            for (int j = 0; j < 2; j++)
                wmma::load_matrix_sync(bf[j], &Bs[cur][k0][wn * 32 + j * 16], 136);
            #pragma unroll
            for (int i = 0; i < 4; i++)
                #pragma unroll
                for (int j = 0; j < 2; j++)
                    wmma::mma_sync(acc[i][j], af[i], bf[j], acc[i][j]);
        }
        __syncthreads();
    }

    // epilogue: rows padded to MPAD, cols padded to SST -> no OOB possible
    #pragma unroll
    for (int i = 0; i < 4; i++) {
        int gr = row0 + wm * 64 + i * 16;
        #pragma unroll
        for (int j = 0; j < 2; j++) {
            int gc = col0 + wn * 32 + j * 16;
            wmma::store_matrix_sync(&d_S[(size_t)gr * SST + gc], acc[i][j], SST, wmma::mem_row_major);
        }
    }
}

// ---------------- copy skip block into d_out ----------------
__global__ void skipcopy_kernel(float* __restrict__ out, int Nn) {
    int idx = blockIdx.x * blockDim.x + threadIdx.x;
    if (idx >= Nn * DD) return;
    int n = idx / DD, c = idx - n * DD;
    out[idx] = d_S[(size_t)n * SST + 900 + c];
}

__global__ void zeroden_kernel(int Nn) {
    int idx = blockIdx.x * blockDim.x + threadIdx.x;
    if (idx < Nn * 4) d_den[idx] = 0.0f;
}

// ---------------- edge pass B ----------------
__global__ void __launch_bounds__(256) edgeB_kernel(const int* __restrict__ EI,
                                                    const float* __restrict__ EA,
                                                    const float* __restrict__ Wcls,
                                                    const float* __restrict__ bcls, int Ee) {
    __shared__ float sWcls[DD * 5];
    __shared__ float sG[8 * DD];
    __shared__ float sW2[2 * DD];
    __shared__ float sBcls[5];
    for (int i = threadIdx.x; i < DD * 5; i += 256) sWcls[i] = Wcls[i];
    for (int i = threadIdx.x; i < 8 * DD; i += 256) sG[i] = d_G8[i];
    for (int i = threadIdx.x; i < 2 * DD; i += 256) sW2[i] = d_W2f[i];
    if (threadIdx.x < 5) sBcls[threadIdx.x] = bcls[threadIdx.x];
    __syncthreads();

    int lane = threadIdx.x & 31;
    int warp = (blockIdx.x * 256 + threadIdx.x) >> 5;
    int nw = (gridDim.x * 256) >> 5;

    for (int e = warp; e < Ee; e += nw) {
        int src = EI[e], dst = EI[Ee + e];
        float ea0 = EA[4 * e + 0], ea1 = EA[4 * e + 1];
        float ea2 = EA[4 * e + 2], ea3 = EA[4 * e + 3];
        const float* rowD = d_S + (size_t)dst * SST;
        const float* rowS = d_S + (size_t)src * SST;

        float l0 = 0, l1 = 0, l2 = 0, l3 = 0, l4 = 0;
        for (int ch = lane; ch < 75; ch += 32) {
            int c = ch * 4;
            float4 cd = *(const float4*)&rowD[1200 + c];
            float4 cs = *(const float4*)&rowS[1500 + c];
            float4 wa = *(const float4*)&sW2[c];
            float4 wb = *(const float4*)&sW2[DD + c];
            float h0 = fast_tanh(cd.x + cs.x + ea2 * wa.x + ea3 * wb.x);
            float h1 = fast_tanh(cd.y + cs.y + ea2 * wa.y + ea3 * wb.y);
            float h2 = fast_tanh(cd.z + cs.z + ea2 * wa.z + ea3 * wb.z);
            float h3 = fast_tanh(cd.w + cs.w + ea2 * wa.w + ea3 * wb.w);
            const float* wc = sWcls + c * 5;
            l0 = fmaf(h0, wc[0], l0); l1 = fmaf(h0, wc[1], l1); l2 = fmaf(h0, wc[2], l2);
            l3 = fmaf(h0, wc[3], l3); l4 = fmaf(h0, wc[4], l4);
            l0 = fmaf(h1, wc[5], l0); l1 = fmaf(h1, wc[6], l1); l2 = fmaf(h1, wc[7], l2);
            l3 = fmaf(h1, wc[8], l3); l4 = fmaf(h1, wc[9], l4);
            l0 = fmaf(h2, wc[10], l0); l1 = fmaf(h2, wc[11], l1); l2 = fmaf(h2, wc[12], l2);
            l3 = fmaf(h2, wc[13], l3); l4 = fmaf(h2, wc[14], l4);
            l0 = fmaf(h3, wc[15], l0); l1 = fmaf(h3, wc[16], l1); l2 = fmaf(h3, wc[17], l2);
            l3 = fmaf(h3, wc[18], l3); l4 = fmaf(h3, wc[19], l4);
        }
        #pragma unroll
        for (int o = 16; o; o >>= 1) {
            l0 += __shfl_xor_sync(0xffffffffu, l0, o);
            l1 += __shfl_xor_sync(0xffffffffu, l1, o);
            l2 += __shfl_xor_sync(0xffffffffu, l2, o);
            l3 += __shfl_xor_sync(0xffffffffu, l3, o);
            l4 += __shfl_xor_sync(0xffffffffu, l4, o);
        }
        l0 += sBcls[0]; l1 += sBcls[1]; l2 += sBcls[2]; l3 += sBcls[3]; l4 += sBcls[4];
        float m = fmaxf(fmaxf(fmaxf(l0, l1), fmaxf(l2, l3)), l4);
        float p0 = __expf(l0 - m), p1 = __expf(l1 - m), p2 = __expf(l2 - m);
        float p3 = __expf(l3 - m), p4 = __expf(l4 - m);
        float inv = 1.0f / (p0 + p1 + p2 + p3 + p4);
        p0 *= inv; p1 *= inv; p2 *= inv; p3 *= inv; p4 *= inv;
        float t0 = ea0 > 0.0f ? 1.0f : 0.0f;
        float t1 = ea1 < 0.0f ? 1.0f : 0.0f;
        if (lane == 0) {
            float* w = d_w8 + e * 8;
            w[0] = p0; w[1] = p1; w[2] = p2; w[3] = p3; w[4] = p4; w[5] = t0; w[6] = t1;
        }

        float a0 = 0, a1 = 0, a2 = 0, a3 = 0;
        for (int ch = lane; ch < 75; ch += 32) {
            int c = ch * 4;
            float4 q = *(const float4*)&rowD[c];
            float4 k4 = *(const float4*)&rowS[300 + c];
            float4 g0 = *(const float4*)&sG[c];
            float4 g1 = *(const float4*)&sG[300 + c];
            float4 g2 = *(const float4*)&sG[600 + c];
            float4 g3 = *(const float4*)&sG[900 + c];
            float4 g4 = *(const float4*)&sG[1200 + c];
            float4 g5 = *(const float4*)&sG[1500 + c];
            float4 g6 = *(const float4*)&sG[1800 + c];
            float4 g7 = *(const float4*)&sG[2100 + c];
            #pragma unroll
            for (int i = 0; i < 4; i++) {
                float gv0 = (&g0.x)[i], gv1 = (&g1.x)[i], gv2 = (&g2.x)[i], gv3 = (&g3.x)[i];
                float gv4 = (&g4.x)[i], gv5 = (&g5.x)[i], gv6 = (&g6.x)[i], gv7 = (&g7.x)[i];
                float ef = gv7;
                ef = fmaf(p0, gv0, ef); ef = fmaf(p1, gv1, ef); ef = fmaf(p2, gv2, ef);
                ef = fmaf(p3, gv3, ef); ef = fmaf(p4, gv4, ef); ef = fmaf(t0, gv5, ef);
                ef = fmaf(t1, gv6, ef);
                float pr = (&q.x)[i] * ((&k4.x)[i] + ef);
                int ci = c + i;
                if (ci < 75) a0 += pr;
                else if (ci < 150) a1 += pr;
                else if (ci < 225) a2 += pr;
                else a3 += pr;
            }
        }
        #pragma unroll
        for (int o = 16; o; o >>= 1) {
            a0 += __shfl_xor_sync(0xffffffffu, a0, o);
            a1 += __shfl_xor_sync(0xffffffffu, a1, o);
            a2 += __shfl_xor_sync(0xffffffffu, a2, o);
            a3 += __shfl_xor_sync(0xffffffffu, a3, o);
        }
        const float sc = 0.115470053837925152f;  // 1/sqrt(75)
        float e0 = __expf(a0 * sc), e1 = __expf(a1 * sc);
        float e2 = __expf(a2 * sc), e3 = __expf(a3 * sc);
        if (lane == 0) {
            float* ep = d_e4 + e * 4;
            ep[0] = e0; ep[1] = e1; ep[2] = e2; ep[3] = e3;
            atomicAdd(&d_den[dst * 4 + 0], e0);
            atomicAdd(&d_den[dst * 4 + 1], e1);
            atomicAdd(&d_den[dst * 4 + 2], e2);
            atomicAdd(&d_den[dst * 4 + 3], e3);
        }
    }
}

// ---------------- edge pass C ----------------
__global__ void __launch_bounds__(256) edgeC_kernel(const int* __restrict__ EI,
                                                    float* __restrict__ out, int Ee) {
    __shared__ float sG[8 * DD];
    for (int i = threadIdx.x; i < 8 * DD; i += 256) sG[i] = d_G8[i];
    __syncthreads();

    int lane = threadIdx.x & 31;
    int warp = (blockIdx.x * 256 + threadIdx.x) >> 5;
    int nw = (gridDim.x * 256) >> 5;

    for (int e = warp; e < Ee; e += nw) {
        int src = EI[e], dst = EI[Ee + e];
        float4 wA = *(const float4*)&d_w8[e * 8];
        float4 wB = *(const float4*)&d_w8[e * 8 + 4];
        float p0 = wA.x, p1 = wA.y, p2 = wA.z, p3 = wA.w, p4 = wB.x, t0 = wB.y, t1 = wB.z;
        float4 ep = *(const float4*)&d_e4[e * 4];
        float4 dn = *(const float4*)&d_den[dst * 4];
        float al0 = __fdividef(ep.x, dn.x);
        float al1 = __fdividef(ep.y, dn.y);
        float al2 = __fdividef(ep.z, dn.z);
        float al3 = __fdividef(ep.w, dn.w);
        const float* rowV = d_S + (size_t)src * SST + 600;
        float* orow = out + (size_t)dst * DD;
        for (int ch = lane; ch < 75; ch += 32) {
            int c = ch * 4;
            float4 v4 = *(const float4*)&rowV[c];
            float4 g0 = *(const float4*)&sG[c];
            float4 g1 = *(const float4*)&sG[300 + c];
            float4 g2 = *(const float4*)&sG[600 + c];
            float4 g3 = *(const float4*)&sG[900 + c];
            float4 g4 = *(const float4*)&sG[1200 + c];
            float4 g5 = *(const float4*)&sG[1500 + c];
            float4 g6 = *(const float4*)&sG[1800 + c];
            float4 g7 = *(const float4*)&sG[2100 + c];
            float r[4];
            #pragma unroll
            for (int i = 0; i < 4; i++) {
                float ef = (&g7.x)[i];
                ef = fmaf(p0, (&g0.x)[i], ef); ef = fmaf(p1, (&g1.x)[i], ef);
                ef = fmaf(p2, (&g2.x)[i], ef); ef = fmaf(p3, (&g3.x)[i], ef);
                ef = fmaf(p4, (&g4.x)[i], ef); ef = fmaf(t0, (&g5.x)[i], ef);
                ef = fmaf(t1, (&g6.x)[i], ef);
                float v = (&v4.x)[i] + ef;
                int ci = c + i;
                float al = ci < 75 ? al0 : (ci < 150 ? al1 : (ci < 225 ? al2 : al3));
                r[i] = v * al;
            }
            asm volatile("red.global.add.v4.f32 [%0], {%1, %2, %3, %4};"
                         :: "l"(&orow[c]), "f"(r[0]), "f"(r[1]), "f"(r[2]), "f"(r[3])
                         : "memory");
        }
    }
}

// ---------------- host launcher ----------------
extern "C" void kernel_launch(void* const* d_in, const int* in_sizes, int n_in,
                              void* d_out, int out_size) {
    const float* x     = (const float*)d_in[0];
    const int*   EI    = (const int*)d_in[1];
    const float* EA    = (const float*)d_in[2];
    const float* nrm   = (const float*)d_in[3];
    const float* Wq    = (const float*)d_in[4];
    const float* bq    = (const float*)d_in[5];
    const float* Wk    = (const float*)d_in[6];
    const float* bk    = (const float*)d_in[7];
    const float* Wv    = (const float*)d_in[8];
    const float* bv    = (const float*)d_in[9];
    const float* We    = (const float*)d_in[10];
    const float* Wn    = (const float*)d_in[11];
    const float* bn    = (const float*)d_in[12];
    const float* Wxy   = (const float*)d_in[13];
    const float* bxy   = (const float*)d_in[14];
    const float* Wloc  = (const float*)d_in[15];
    const float* bloc  = (const float*)d_in[16];
    const float* Wobj  = (const float*)d_in[17];
    const float* bobj  = (const float*)d_in[18];
    const float* Wfus  = (const float*)d_in[19];
    const float* bfus  = (const float*)d_in[20];
    const float* Wcls  = (const float*)d_in[21];
    const float* bcls  = (const float*)d_in[22];
    const float* Wskip = (const float*)d_in[23];
    const float* bskip = (const float*)d_in[24];
    const float* vocab = (const float*)d_in[25];

    int Nn = in_sizes[0] / DD;
    int Ee = in_sizes[1] / 2;
    float* out = (float*)d_out;

    fold1_kernel<<<(DD + 127) / 128, 128>>>(Wn, Wxy, Wloc, Wfus, vocab, bxy, bn, bobj, bloc, bfus);
    fold2_kernel<<<(DD + 127) / 128, 128>>>(We);
    buildA_kernel<<<(Nn * KK + 255) / 256, 256>>>(x, nrm, Nn);
    buildW_kernel<<<(KK * NCOLS + 255) / 256, 256>>>(Wq, Wk, Wv, Wskip, Wobj, bq, bk, bv, bskip);

    dim3 gg((NCOLS + 127) / 128, (Nn + 127) / 128);
    gemm_tf32_kernel<<<gg, 256>>>(Nn);

    skipcopy_kernel<<<(Nn * DD + 255) / 256, 256>>>(out, Nn);
    zeroden_kernel<<<(Nn * 4 + 255) / 256, 256>>>(Nn);

    edgeB_kernel<<<2048, 256>>>(EI, EA, Wcls, bcls, Ee);
    edgeC_kernel<<<2048, 256>>>(EI, out, Ee);
}

// round 4
// speedup vs baseline: 1.2368x; 1.0752x over previous
#include <cuda_runtime.h>
#include <mma.h>
#include <math.h>
#include <stdint.h>

using namespace nvcuda;

#define DD 300
#define NCOLS 1800
#define KK 304
#define MAXN 50000
#define MAXE 250000
#define MPAD 50048          // 391 * 128
#define SST  1920           // padded row stride of d_S
#define WST  1920           // padded col stride of d_Wbig
#define STAGES 4
#define KT 16

// ---- static scratch (allocation-free rule: __device__ globals) ----
__device__ float d_Apad[(size_t)MPAD * KK];    // [MPAD][304], tf32-rounded
__device__ float d_Wbig[(size_t)KK * WST];     // [304][1920], tf32-rounded
__device__ float d_S[(size_t)MPAD * SST];      // [N][1920] = Q|K|V|skip|Cd|Cs|pad
__device__ float d_w8[MAXE * 8];               // prob(5), t0, t1
__device__ float d_e4[MAXE * 4];               // exp(alpha) per head
__device__ float d_den[MAXN * 4];              // softmax denominators
__device__ float d_NLi[3 * DD];
__device__ float d_NLj[3 * DD];
__device__ float d_W2f[2 * DD];
__device__ float d_c0[DD];
__device__ float d_T8[8 * DD];
__device__ float d_G8[8 * DD];

__device__ __forceinline__ float fast_tanh(float x) {
    float r;
    asm("tanh.approx.f32 %0, %1;" : "=f"(r) : "f"(x));
    return r;
}
__device__ __forceinline__ float to_tf32(float x) {
    float r;
    asm("cvt.rna.tf32.f32 %0, %1;" : "=f"(r) : "f"(x));
    return r;
}

// ---------------- fold 1: small matrix foldings ----------------
__global__ void fold1_kernel(const float* __restrict__ Wn, const float* __restrict__ Wxy,
                             const float* __restrict__ Wloc, const float* __restrict__ Wfus,
                             const float* __restrict__ vocab, const float* __restrict__ bxy,
                             const float* __restrict__ bn, const float* __restrict__ bobj,
                             const float* __restrict__ bloc, const float* __restrict__ bfus) {
    int c = blockIdx.x * blockDim.x + threadIdx.x;
    if (c >= DD) return;
    float nli0 = 0, nli1 = 0, nli2 = 0, nlj0 = 0, nlj1 = 0, nlj2 = 0;
    float w20 = 0, w21 = 0, c0 = 0;
    float t0 = 0, t1 = 0, t2 = 0, t3 = 0, t4 = 0, t5 = 0, t6 = 0;
    for (int k = 0; k < DD; k++) {
        float wl0 = Wloc[k * DD + c];
        float wl1 = Wloc[(DD + k) * DD + c];
        float wl2 = Wloc[(2 * DD + k) * DD + c];
        float wn0 = Wn[k], wn1 = Wn[DD + k], wn2 = Wn[2 * DD + k];
        nli0 = fmaf(wn0, wl1, nli0); nli1 = fmaf(wn1, wl1, nli1); nli2 = fmaf(wn2, wl1, nli2);
        nlj0 = fmaf(wn0, wl2, nlj0); nlj1 = fmaf(wn1, wl2, nlj1); nlj2 = fmaf(wn2, wl2, nlj2);
        w20 = fmaf(Wxy[k], wl0, w20); w21 = fmaf(Wxy[DD + k], wl0, w21);
        c0 = fmaf(bxy[k], wl0, c0);
        c0 = fmaf(bn[k], wl1 + wl2, c0);
        float wf0 = Wfus[k * DD + c];
        float wf1 = Wfus[(DD + k) * DD + c];
        t0 = fmaf(vocab[2 * DD + k], wf1, t0);
        t1 = fmaf(vocab[3 * DD + k], wf1, t1);
        t2 = fmaf(vocab[4 * DD + k], wf1, t2);
        t3 = fmaf(vocab[5 * DD + k], wf1, t3);
        t4 = fmaf(vocab[6 * DD + k], wf1, t4);
        t5 = fmaf(vocab[k], wf0, t5);
        t6 = fmaf(vocab[DD + k], wf0, t6);
    }
    d_NLi[0 * DD + c] = nli0; d_NLi[1 * DD + c] = nli1; d_NLi[2 * DD + c] = nli2;
    d_NLj[0 * DD + c] = nlj0; d_NLj[1 * DD + c] = nlj1; d_NLj[2 * DD + c] = nlj2;
    d_W2f[c] = w20; d_W2f[DD + c] = w21;
    d_c0[c] = c0 + bobj[c] + bloc[c];
    d_T8[0 * DD + c] = t0; d_T8[1 * DD + c] = t1; d_T8[2 * DD + c] = t2;
    d_T8[3 * DD + c] = t3; d_T8[4 * DD + c] = t4; d_T8[5 * DD + c] = t5;
    d_T8[6 * DD + c] = t6; d_T8[7 * DD + c] = bfus[c];
}

// ---------------- fold 2: G8 = T8 @ We ----------------
__global__ void fold2_kernel(const float* __restrict__ We) {
    int c = blockIdx.x * blockDim.x + threadIdx.x;
    if (c >= DD) return;
    float g[8] = {0, 0, 0, 0, 0, 0, 0, 0};
    for (int k = 0; k < DD; k++) {
        float w = We[k * DD + c];
        #pragma unroll
        for (int j = 0; j < 8; j++) g[j] = fmaf(d_T8[j * DD + k], w, g[j]);
    }
    #pragma unroll
    for (int j = 0; j < 8; j++) d_G8[j * DD + c] = g[j];
}

// ---------------- build A (padded, tf32-rounded) ----------------
__global__ void buildA_kernel(const float* __restrict__ x, const float* __restrict__ nrm, int Nn) {
    int idx = blockIdx.x * blockDim.x + threadIdx.x;
    if (idx >= MPAD * KK) return;
    int n = idx / KK, k = idx - n * KK;
    float v = 0.0f;
    if (n < Nn) {
        if (k < DD) v = to_tf32(x[n * DD + k]);
        else if (k < DD + 3) v = to_tf32(nrm[n * 3 + (k - DD)]);
        else v = 1.0f;
    }
    d_Apad[idx] = v;
}

// ---------------- build Wbig (padded, tf32-rounded) ----------------
__global__ void buildW_kernel(const float* __restrict__ Wq, const float* __restrict__ Wk,
                              const float* __restrict__ Wv, const float* __restrict__ Wskip,
                              const float* __restrict__ Wobj, const float* __restrict__ bq,
                              const float* __restrict__ bk, const float* __restrict__ bv,
                              const float* __restrict__ bskip) {
    int idx = blockIdx.x * blockDim.x + threadIdx.x;
    if (idx >= KK * WST) return;
    int k = idx / WST, c = idx - k * WST;
    float v = 0.0f;
    if (c < NCOLS) {
        int b = c / DD, cc = c - b * DD;
        if (k < DD) {
            if (b == 0) v = Wq[k * DD + cc];
            else if (b == 1) v = Wk[k * DD + cc];
            else if (b == 2) v = Wv[k * DD + cc];
            else if (b == 3) v = Wskip[k * DD + cc];
            else if (b == 4) v = Wobj[k * DD + cc] - Wobj[(DD + k) * DD + cc];
            else v = Wobj[(DD + k) * DD + cc];
        } else if (k < DD + 3) {
            int r = k - DD;
            if (b == 4) v = d_NLi[r * DD + cc];
            else if (b == 5) v = d_NLj[r * DD + cc];
        } else {
            if (b == 0) v = bq[cc];
            else if (b == 1) v = bk[cc];
            else if (b == 2) v = bv[cc];
            else if (b == 3) v = bskip[cc];
            else if (b == 4) v = d_c0[cc];
        }
        v = to_tf32(v);
    }
    d_Wbig[idx] = v;
}

// ---------------- node GEMM (tf32 wmma, cp.async 4-stage): S = Apad @ Wbig ----------------
__global__ void __launch_bounds__(256, 2) gemm_tf32_kernel() {
    extern __shared__ float sm[];
    float (*As)[128][24] = (float (*)[128][24])sm;                       // STAGES x 128 x 24
    float (*Bs)[16][136] = (float (*)[16][136])(sm + STAGES * 128 * 24); // STAGES x 16 x 136

    int tid = threadIdx.x;
    int wid = tid >> 5;
    int wm = wid >> 2;            // 0..1
    int wn = wid & 3;             // 0..3
    int row0 = blockIdx.y * 128, col0 = blockIdx.x * 128;

    // loader indices: each thread copies 8 consecutive floats (2 x 16B)
    int arow = tid >> 1;
    int akoff = (tid & 1) * 8;
    int brow = tid >> 4;
    int bcoff = (tid & 15) * 8;

    const float* agp = &d_Apad[(size_t)(row0 + arow) * KK + akoff];
    const float* bgp = &d_Wbig[(size_t)brow * WST + col0 + bcoff];

    wmma::fragment<wmma::accumulator, 16, 16, 8, float> acc[4][2];
    #pragma unroll
    for (int i = 0; i < 4; i++)
        #pragma unroll
        for (int j = 0; j < 2; j++) wmma::fill_fragment(acc[i][j], 0.0f);

    auto loadStage = [&](int st, int kt) {
        uint32_t da = (uint32_t)__cvta_generic_to_shared(&As[st][arow][akoff]);
        const float* sa = agp + kt;
        asm volatile("cp.async.cg.shared.global [%0], [%1], 16;\n\t"
                     "cp.async.cg.shared.global [%2], [%3], 16;"
                     :: "r"(da), "l"(sa), "r"(da + 16), "l"(sa + 4));
        uint32_t db = (uint32_t)__cvta_generic_to_shared(&Bs[st][brow][bcoff]);
        const float* sb = bgp + (size_t)kt * WST;
        asm volatile("cp.async.cg.shared.global [%0], [%1], 16;\n\t"
                     "cp.async.cg.shared.global [%2], [%3], 16;"
                     :: "r"(db), "l"(sb), "r"(db + 16), "l"(sb + 4));
    };

    const int NT = KK / KT;  // 19
    #pragma unroll
    for (int i = 0; i < STAGES - 1; i++) {
        loadStage(i, i * KT);
        asm volatile("cp.async.commit_group;");
    }

    for (int s = 0; s < NT; s++) {
        asm volatile("cp.async.wait_group %0;" :: "n"(STAGES - 2));
        __syncthreads();
        int ld = s + STAGES - 1;
        if (ld < NT) loadStage(ld & (STAGES - 1), ld * KT);
        asm volatile("cp.async.commit_group;");

        int st = s & (STAGES - 1);
        #pragma unroll
        for (int ks = 0; ks < 2; ks++) {
            int k0 = ks * 8;
            wmma::fragment<wmma::matrix_a, 16, 16, 8, wmma::precision::tf32, wmma::row_major> af[4];
            wmma::fragment<wmma::matrix_b, 16, 16, 8, wmma::precision::tf32, wmma::row_major> bf[2];
            #pragma unroll
            for (int i = 0; i < 4; i++)
                wmma::load_matrix_sync(af[i], &As[st][wm * 64 + i * 16][k0], 24);
            #pragma unroll
            for (int j = 0; j < 2; j++)
                wmma::load_matrix_sync(bf[j], &Bs[st][k0][wn * 32 + j * 16], 136);
            #pragma unroll
            for (int i = 0; i < 4; i++)
                #pragma unroll
                for (int j = 0; j < 2; j++)
                    wmma::mma_sync(acc[i][j], af[i], bf[j], acc[i][j]);
        }
    }

    #pragma unroll
    for (int i = 0; i < 4; i++) {
        int gr = row0 + wm * 64 + i * 16;
        #pragma unroll
        for (int j = 0; j < 2; j++) {
            int gc = col0 + wn * 32 + j * 16;
            wmma::store_matrix_sync(&d_S[(size_t)gr * SST + gc], acc[i][j], SST, wmma::mem_row_major);
        }
    }
}

// ---------------- copy skip block into d_out ----------------
__global__ void skipcopy_kernel(float* __restrict__ out, int Nn) {
    int idx = blockIdx.x * blockDim.x + threadIdx.x;
    if (idx >= Nn * DD) return;
    int n = idx / DD, c = idx - n * DD;
    out[idx] = d_S[(size_t)n * SST + 900 + c];
}

__global__ void zeroden_kernel(int Nn) {
    int idx = blockIdx.x * blockDim.x + threadIdx.x;
    if (idx < Nn * 4) d_den[idx] = 0.0f;
}

// ---------------- edge pass B ----------------
__global__ void __launch_bounds__(256) edgeB_kernel(const int* __restrict__ EI,
                                                    const float* __restrict__ EA,
                                                    const float* __restrict__ Wcls,
                                                    const float* __restrict__ bcls, int Ee) {
    __shared__ float sWcls[DD * 5];
    __shared__ float sG[8 * DD];
    __shared__ float sW2[2 * DD];
    __shared__ float sBcls[5];
    for (int i = threadIdx.x; i < DD * 5; i += 256) sWcls[i] = Wcls[i];
    for (int i = threadIdx.x; i < 8 * DD; i += 256) sG[i] = d_G8[i];
    for (int i = threadIdx.x; i < 2 * DD; i += 256) sW2[i] = d_W2f[i];
    if (threadIdx.x < 5) sBcls[threadIdx.x] = bcls[threadIdx.x];
    __syncthreads();

    int lane = threadIdx.x & 31;
    int warp = (blockIdx.x * 256 + threadIdx.x) >> 5;
    int nw = (gridDim.x * 256) >> 5;

    for (int e = warp; e < Ee; e += nw) {
        int src = __ldg(&EI[e]), dst = __ldg(&EI[Ee + e]);
        float4 ea = __ldg((const float4*)&EA[4 * e]);
        float ea0 = ea.x, ea1 = ea.y, ea2 = ea.z, ea3 = ea.w;
        const float* rowD = d_S + (size_t)dst * SST;
        const float* rowS = d_S + (size_t)src * SST;

        float l0 = 0, l1 = 0, l2 = 0, l3 = 0, l4 = 0;
        for (int ch = lane; ch < 75; ch += 32) {
            int c = ch * 4;
            float4 cd = __ldg((const float4*)&rowD[1200 + c]);
            float4 cs = __ldg((const float4*)&rowS[1500 + c]);
            float4 wa = *(const float4*)&sW2[c];
            float4 wb = *(const float4*)&sW2[DD + c];
            float h0 = fast_tanh(cd.x + cs.x + ea2 * wa.x + ea3 * wb.x);
            float h1 = fast_tanh(cd.y + cs.y + ea2 * wa.y + ea3 * wb.y);
            float h2 = fast_tanh(cd.z + cs.z + ea2 * wa.z + ea3 * wb.z);
            float h3 = fast_tanh(cd.w + cs.w + ea2 * wa.w + ea3 * wb.w);
            const float* wc = sWcls + c * 5;
            l0 = fmaf(h0, wc[0], l0); l1 = fmaf(h0, wc[1], l1); l2 = fmaf(h0, wc[2], l2);
            l3 = fmaf(h0, wc[3], l3); l4 = fmaf(h0, wc[4], l4);
            l0 = fmaf(h1, wc[5], l0); l1 = fmaf(h1, wc[6], l1); l2 = fmaf(h1, wc[7], l2);
            l3 = fmaf(h1, wc[8], l3); l4 = fmaf(h1, wc[9], l4);
            l0 = fmaf(h2, wc[10], l0); l1 = fmaf(h2, wc[11], l1); l2 = fmaf(h2, wc[12], l2);
            l3 = fmaf(h2, wc[13], l3); l4 = fmaf(h2, wc[14], l4);
            l0 = fmaf(h3, wc[15], l0); l1 = fmaf(h3, wc[16], l1); l2 = fmaf(h3, wc[17], l2);
            l3 = fmaf(h3, wc[18], l3); l4 = fmaf(h3, wc[19], l4);
        }
        #pragma unroll
        for (int o = 16; o; o >>= 1) {
            l0 += __shfl_xor_sync(0xffffffffu, l0, o);
            l1 += __shfl_xor_sync(0xffffffffu, l1, o);
            l2 += __shfl_xor_sync(0xffffffffu, l2, o);
            l3 += __shfl_xor_sync(0xffffffffu, l3, o);
            l4 += __shfl_xor_sync(0xffffffffu, l4, o);
        }
        l0 += sBcls[0]; l1 += sBcls[1]; l2 += sBcls[2]; l3 += sBcls[3]; l4 += sBcls[4];
        float m = fmaxf(fmaxf(fmaxf(l0, l1), fmaxf(l2, l3)), l4);
        float p0 = __expf(l0 - m), p1 = __expf(l1 - m), p2 = __expf(l2 - m);
        float p3 = __expf(l3 - m), p4 = __expf(l4 - m);
        float inv = 1.0f / (p0 + p1 + p2 + p3 + p4);
        p0 *= inv; p1 *= inv; p2 *= inv; p3 *= inv; p4 *= inv;
        float t0 = ea0 > 0.0f ? 1.0f : 0.0f;
        float t1 = ea1 < 0.0f ? 1.0f : 0.0f;
        if (lane == 0) {
            *(float4*)&d_w8[e * 8] = make_float4(p0, p1, p2, p3);
            *(float4*)&d_w8[e * 8 + 4] = make_float4(p4, t0, t1, 0.0f);
        }

        float a0 = 0, a1 = 0, a2 = 0, a3 = 0;
        for (int ch = lane; ch < 75; ch += 32) {
            int c = ch * 4;
            float4 q = __ldg((const float4*)&rowD[c]);
            float4 k4 = __ldg((const float4*)&rowS[300 + c]);
            float4 g0 = *(const float4*)&sG[c];
            float4 g1 = *(const float4*)&sG[300 + c];
            float4 g2 = *(const float4*)&sG[600 + c];
            float4 g3 = *(const float4*)&sG[900 + c];
            float4 g4 = *(const float4*)&sG[1200 + c];
            float4 g5 = *(const float4*)&sG[1500 + c];
            float4 g6 = *(const float4*)&sG[1800 + c];
            float4 g7 = *(const float4*)&sG[2100 + c];
            #pragma unroll
            for (int i = 0; i < 4; i++) {
                float ef = (&g7.x)[i];
                ef = fmaf(p0, (&g0.x)[i], ef); ef = fmaf(p1, (&g1.x)[i], ef);
                ef = fmaf(p2, (&g2.x)[i], ef); ef = fmaf(p3, (&g3.x)[i], ef);
                ef = fmaf(p4, (&g4.x)[i], ef); ef = fmaf(t0, (&g5.x)[i], ef);
                ef = fmaf(t1, (&g6.x)[i], ef);
                float pr = (&q.x)[i] * ((&k4.x)[i] + ef);
                int ci = c + i;
                if (ci < 75) a0 += pr;
                else if (ci < 150) a1 += pr;
                else if (ci < 225) a2 += pr;
                else a3 += pr;
            }
        }
        #pragma unroll
        for (int o = 16; o; o >>= 1) {
            a0 += __shfl_xor_sync(0xffffffffu, a0, o);
            a1 += __shfl_xor_sync(0xffffffffu, a1, o);
            a2 += __shfl_xor_sync(0xffffffffu, a2, o);
            a3 += __shfl_xor_sync(0xffffffffu, a3, o);
        }
        const float sc = 0.115470053837925152f;  // 1/sqrt(75)
        float e0 = __expf(a0 * sc), e1 = __expf(a1 * sc);
        float e2 = __expf(a2 * sc), e3 = __expf(a3 * sc);
        if (lane == 0) {
            *(float4*)&d_e4[e * 4] = make_float4(e0, e1, e2, e3);
            atomicAdd(&d_den[dst * 4 + 0], e0);
            atomicAdd(&d_den[dst * 4 + 1], e1);
            atomicAdd(&d_den[dst * 4 + 2], e2);
            atomicAdd(&d_den[dst * 4 + 3], e3);
        }
    }
}

// ---------------- edge pass C ----------------
__global__ void __launch_bounds__(256) edgeC_kernel(const int* __restrict__ EI,
                                                    float* __restrict__ out, int Ee) {
    __shared__ float sG[8 * DD];
    for (int i = threadIdx.x; i < 8 * DD; i += 256) sG[i] = d_G8[i];
    __syncthreads();

    int lane = threadIdx.x & 31;
    int warp = (blockIdx.x * 256 + threadIdx.x) >> 5;
    int nw = (gridDim.x * 256) >> 5;

    for (int e = warp; e < Ee; e += nw) {
        int src = __ldg(&EI[e]), dst = __ldg(&EI[Ee + e]);
        float4 wA = __ldg((const float4*)&d_w8[e * 8]);
        float4 wB = __ldg((const float4*)&d_w8[e * 8 + 4]);
        float p0 = wA.x, p1 = wA.y, p2 = wA.z, p3 = wA.w, p4 = wB.x, t0 = wB.y, t1 = wB.z;
        float4 ep = __ldg((const float4*)&d_e4[e * 4]);
        float4 dn = __ldg((const float4*)&d_den[dst * 4]);
        float al0 = __fdividef(ep.x, dn.x);
        float al1 = __fdividef(ep.y, dn.y);
        float al2 = __fdividef(ep.z, dn.z);
        float al3 = __fdividef(ep.w, dn.w);
        const float* rowV = d_S + (size_t)src * SST + 600;
        float* orow = out + (size_t)dst * DD;
        for (int ch = lane; ch < 75; ch += 32) {
            int c = ch * 4;
            float4 v4 = __ldg((const float4*)&rowV[c]);
            float4 g0 = *(const float4*)&sG[c];
            float4 g1 = *(const float4*)&sG[300 + c];
            float4 g2 = *(const float4*)&sG[600 + c];
            float4 g3 = *(const float4*)&sG[900 + c];
            float4 g4 = *(const float4*)&sG[1200 + c];
            float4 g5 = *(const float4*)&sG[1500 + c];
            float4 g6 = *(const float4*)&sG[1800 + c];
            float4 g7 = *(const float4*)&sG[2100 + c];
            float r[4];
            #pragma unroll
            for (int i = 0; i < 4; i++) {
                float ef = (&g7.x)[i];
                ef = fmaf(p0, (&g0.x)[i], ef); ef = fmaf(p1, (&g1.x)[i], ef);
                ef = fmaf(p2, (&g2.x)[i], ef); ef = fmaf(p3, (&g3.x)[i], ef);
                ef = fmaf(p4, (&g4.x)[i], ef); ef = fmaf(t0, (&g5.x)[i], ef);
                ef = fmaf(t1, (&g6.x)[i], ef);
                float v = (&v4.x)[i] + ef;
                int ci = c + i;
                float al = ci < 75 ? al0 : (ci < 150 ? al1 : (ci < 225 ? al2 : al3));
                r[i] = v * al;
            }
            asm volatile("red.global.add.v4.f32 [%0], {%1, %2, %3, %4};"
                         :: "l"(&orow[c]), "f"(r[0]), "f"(r[1]), "f"(r[2]), "f"(r[3])
                         : "memory");
        }
    }
}

// ---------------- host launcher ----------------
extern "C" void kernel_launch(void* const* d_in, const int* in_sizes, int n_in,
                              void* d_out, int out_size) {
    const float* x     = (const float*)d_in[0];
    const int*   EI    = (const int*)d_in[1];
    const float* EA    = (const float*)d_in[2];
    const float* nrm   = (const float*)d_in[3];
    const float* Wq    = (const float*)d_in[4];
    const float* bq    = (const float*)d_in[5];
    const float* Wk    = (const float*)d_in[6];
    const float* bk    = (const float*)d_in[7];
    const float* Wv    = (const float*)d_in[8];
    const float* bv    = (const float*)d_in[9];
    const float* We    = (const float*)d_in[10];
    const float* Wn    = (const float*)d_in[11];
    const float* bn    = (const float*)d_in[12];
    const float* Wxy   = (const float*)d_in[13];
    const float* bxy   = (const float*)d_in[14];
    const float* Wloc  = (const float*)d_in[15];
    const float* bloc  = (const float*)d_in[16];
    const float* Wobj  = (const float*)d_in[17];
    const float* bobj  = (const float*)d_in[18];
    const float* Wfus  = (const float*)d_in[19];
    const float* bfus  = (const float*)d_in[20];
    const float* Wcls  = (const float*)d_in[21];
    const float* bcls  = (const float*)d_in[22];
    const float* Wskip = (const float*)d_in[23];
    const float* bskip = (const float*)d_in[24];
    const float* vocab = (const float*)d_in[25];

    int Nn = in_sizes[0] / DD;
    int Ee = in_sizes[1] / 2;
    float* out = (float*)d_out;

    static bool attr_set = false;
    const int smem_bytes = STAGES * (128 * 24 + 16 * 136) * 4;  // 83968
    if (!attr_set) {
        cudaFuncSetAttribute(gemm_tf32_kernel, cudaFuncAttributeMaxDynamicSharedMemorySize, smem_bytes);
        attr_set = true;
    }

    fold1_kernel<<<(DD + 127) / 128, 128>>>(Wn, Wxy, Wloc, Wfus, vocab, bxy, bn, bobj, bloc, bfus);
    fold2_kernel<<<(DD + 127) / 128, 128>>>(We);
    buildA_kernel<<<(MPAD * KK + 255) / 256, 256>>>(x, nrm, Nn);
    buildW_kernel<<<(KK * WST + 255) / 256, 256>>>(Wq, Wk, Wv, Wskip, Wobj, bq, bk, bv, bskip);

    dim3 gg(WST / 128, MPAD / 128);  // 15 x 391
    gemm_tf32_kernel<<<gg, 256, smem_bytes>>>();

    skipcopy_kernel<<<(Nn * DD + 255) / 256, 256>>>(out, Nn);
    zeroden_kernel<<<(Nn * 4 + 255) / 256, 256>>>(Nn);

    edgeB_kernel<<<2048, 256>>>(EI, EA, Wcls, bcls, Ee);
    edgeC_kernel<<<2048, 256>>>(EI, out, Ee);
}

// round 5
// speedup vs baseline: 1.2845x; 1.0386x over previous
#include <cuda_runtime.h>
#include <mma.h>
#include <math.h>
#include <stdint.h>

using namespace nvcuda;

#define DD 300
#define NCOLS 1800
#define KK 304
#define MAXN 50000
#define MAXE 250000
#define MPAD 50048          // 391 * 128
#define SST  1920           // padded row stride of d_S
#define WST  1920           // padded col stride of d_Wbig
#define STAGES 4
#define KT 16

// ---- static scratch (allocation-free rule: __device__ globals) ----
__device__ float d_Apad[(size_t)MPAD * KK];    // [MPAD][304], tf32-rounded
__device__ float d_Wbig[(size_t)KK * WST];     // [304][1920], tf32-rounded
__device__ float d_S[(size_t)MPAD * SST];      // [N][1920] = Q|K|V|skip|Cd|Cs|pad
__device__ float d_NLi[3 * DD];
__device__ float d_NLj[3 * DD];
__device__ float d_W2f[2 * DD];
__device__ float d_c0[DD];
__device__ float d_T8[8 * DD];
__device__ float d_G8[8 * DD];
// CSR scratch
__device__ int  d_deg[MAXN];
__device__ int  d_rowptr[MAXN + 1];
__device__ int  d_cursor[MAXN];
__device__ int  d_blksum[256];
__device__ int2 d_edges[MAXE];                 // (src, e) grouped by dst

__device__ __forceinline__ float fast_tanh(float x) {
    float r;
    asm("tanh.approx.f32 %0, %1;" : "=f"(r) : "f"(x));
    return r;
}
__device__ __forceinline__ float to_tf32(float x) {
    float r;
    asm("cvt.rna.tf32.f32 %0, %1;" : "=f"(r) : "f"(x));
    return r;
}

// ---------------- fold 1: small matrix foldings ----------------
__global__ void fold1_kernel(const float* __restrict__ Wn, const float* __restrict__ Wxy,
                             const float* __restrict__ Wloc, const float* __restrict__ Wfus,
                             const float* __restrict__ vocab, const float* __restrict__ bxy,
                             const float* __restrict__ bn, const float* __restrict__ bobj,
                             const float* __restrict__ bloc, const float* __restrict__ bfus) {
    int c = blockIdx.x * blockDim.x + threadIdx.x;
    if (c >= DD) return;
    float nli0 = 0, nli1 = 0, nli2 = 0, nlj0 = 0, nlj1 = 0, nlj2 = 0;
    float w20 = 0, w21 = 0, c0 = 0;
    float t0 = 0, t1 = 0, t2 = 0, t3 = 0, t4 = 0, t5 = 0, t6 = 0;
    for (int k = 0; k < DD; k++) {
        float wl0 = Wloc[k * DD + c];
        float wl1 = Wloc[(DD + k) * DD + c];
        float wl2 = Wloc[(2 * DD + k) * DD + c];
        float wn0 = Wn[k], wn1 = Wn[DD + k], wn2 = Wn[2 * DD + k];
        nli0 = fmaf(wn0, wl1, nli0); nli1 = fmaf(wn1, wl1, nli1); nli2 = fmaf(wn2, wl1, nli2);
        nlj0 = fmaf(wn0, wl2, nlj0); nlj1 = fmaf(wn1, wl2, nlj1); nlj2 = fmaf(wn2, wl2, nlj2);
        w20 = fmaf(Wxy[k], wl0, w20); w21 = fmaf(Wxy[DD + k], wl0, w21);
        c0 = fmaf(bxy[k], wl0, c0);
        c0 = fmaf(bn[k], wl1 + wl2, c0);
        float wf0 = Wfus[k * DD + c];
        float wf1 = Wfus[(DD + k) * DD + c];
        t0 = fmaf(vocab[2 * DD + k], wf1, t0);
        t1 = fmaf(vocab[3 * DD + k], wf1, t1);
        t2 = fmaf(vocab[4 * DD + k], wf1, t2);
        t3 = fmaf(vocab[5 * DD + k], wf1, t3);
        t4 = fmaf(vocab[6 * DD + k], wf1, t4);
        t5 = fmaf(vocab[k], wf0, t5);
        t6 = fmaf(vocab[DD + k], wf0, t6);
    }
    d_NLi[0 * DD + c] = nli0; d_NLi[1 * DD + c] = nli1; d_NLi[2 * DD + c] = nli2;
    d_NLj[0 * DD + c] = nlj0; d_NLj[1 * DD + c] = nlj1; d_NLj[2 * DD + c] = nlj2;
    d_W2f[c] = w20; d_W2f[DD + c] = w21;
    d_c0[c] = c0 + bobj[c] + bloc[c];
    d_T8[0 * DD + c] = t0; d_T8[1 * DD + c] = t1; d_T8[2 * DD + c] = t2;
    d_T8[3 * DD + c] = t3; d_T8[4 * DD + c] = t4; d_T8[5 * DD + c] = t5;
    d_T8[6 * DD + c] = t6; d_T8[7 * DD + c] = bfus[c];
}

// ---------------- fold 2: G8 = T8 @ We ----------------
__global__ void fold2_kernel(const float* __restrict__ We) {
    int c = blockIdx.x * blockDim.x + threadIdx.x;
    if (c >= DD) return;
    float g[8] = {0, 0, 0, 0, 0, 0, 0, 0};
    for (int k = 0; k < DD; k++) {
        float w = We[k * DD + c];
        #pragma unroll
        for (int j = 0; j < 8; j++) g[j] = fmaf(d_T8[j * DD + k], w, g[j]);
    }
    #pragma unroll
    for (int j = 0; j < 8; j++) d_G8[j * DD + c] = g[j];
}

// ---------------- build A (tf32-rounded; pad rows stay zero) ----------------
__global__ void buildA_kernel(const float* __restrict__ x, const float* __restrict__ nrm, int Nn) {
    int idx = blockIdx.x * blockDim.x + threadIdx.x;
    if (idx >= Nn * KK) return;
    int n = idx / KK, k = idx - n * KK;
    float v;
    if (k < DD) v = to_tf32(x[n * DD + k]);
    else if (k < DD + 3) v = to_tf32(nrm[n * 3 + (k - DD)]);
    else v = 1.0f;
    d_Apad[idx] = v;
}

// ---------------- build Wbig (padded, tf32-rounded) ----------------
__global__ void buildW_kernel(const float* __restrict__ Wq, const float* __restrict__ Wk,
                              const float* __restrict__ Wv, const float* __restrict__ Wskip,
                              const float* __restrict__ Wobj, const float* __restrict__ bq,
                              const float* __restrict__ bk, const float* __restrict__ bv,
                              const float* __restrict__ bskip) {
    int idx = blockIdx.x * blockDim.x + threadIdx.x;
    if (idx >= KK * WST) return;
    int k = idx / WST, c = idx - k * WST;
    float v = 0.0f;
    if (c < NCOLS) {
        int b = c / DD, cc = c - b * DD;
        if (k < DD) {
            if (b == 0) v = Wq[k * DD + cc];
            else if (b == 1) v = Wk[k * DD + cc];
            else if (b == 2) v = Wv[k * DD + cc];
            else if (b == 3) v = Wskip[k * DD + cc];
            else if (b == 4) v = Wobj[k * DD + cc] - Wobj[(DD + k) * DD + cc];
            else v = Wobj[(DD + k) * DD + cc];
        } else if (k < DD + 3) {
            int r = k - DD;
            if (b == 4) v = d_NLi[r * DD + cc];
            else if (b == 5) v = d_NLj[r * DD + cc];
        } else {
            if (b == 0) v = bq[cc];
            else if (b == 1) v = bk[cc];
            else if (b == 2) v = bv[cc];
            else if (b == 3) v = bskip[cc];
            else if (b == 4) v = d_c0[cc];
        }
        v = to_tf32(v);
    }
    d_Wbig[idx] = v;
}

// ---------------- node GEMM (tf32 wmma, cp.async 4-stage): S = Apad @ Wbig ----------------
__global__ void __launch_bounds__(256, 2) gemm_tf32_kernel() {
    extern __shared__ float sm[];
    float (*As)[128][24] = (float (*)[128][24])sm;
    float (*Bs)[16][136] = (float (*)[16][136])(sm + STAGES * 128 * 24);

    int tid = threadIdx.x;
    int wid = tid >> 5;
    int wm = wid >> 2;
    int wn = wid & 3;
    int row0 = blockIdx.y * 128, col0 = blockIdx.x * 128;

    int arow = tid >> 1;
    int akoff = (tid & 1) * 8;
    int brow = tid >> 4;
    int bcoff = (tid & 15) * 8;

    const float* agp = &d_Apad[(size_t)(row0 + arow) * KK + akoff];
    const float* bgp = &d_Wbig[(size_t)brow * WST + col0 + bcoff];

    wmma::fragment<wmma::accumulator, 16, 16, 8, float> acc[4][2];
    #pragma unroll
    for (int i = 0; i < 4; i++)
        #pragma unroll
        for (int j = 0; j < 2; j++) wmma::fill_fragment(acc[i][j], 0.0f);

    auto loadStage = [&](int st, int kt) {
        uint32_t da = (uint32_t)__cvta_generic_to_shared(&As[st][arow][akoff]);
        const float* sa = agp + kt;
        asm volatile("cp.async.cg.shared.global [%0], [%1], 16;\n\t"
                     "cp.async.cg.shared.global [%2], [%3], 16;"
                     :: "r"(da), "l"(sa), "r"(da + 16), "l"(sa + 4));
        uint32_t db = (uint32_t)__cvta_generic_to_shared(&Bs[st][brow][bcoff]);
        const float* sb = bgp + (size_t)kt * WST;
        asm volatile("cp.async.cg.shared.global [%0], [%1], 16;\n\t"
                     "cp.async.cg.shared.global [%2], [%3], 16;"
                     :: "r"(db), "l"(sb), "r"(db + 16), "l"(sb + 4));
    };

    const int NT = KK / KT;  // 19
    #pragma unroll
    for (int i = 0; i < STAGES - 1; i++) {
        loadStage(i, i * KT);
        asm volatile("cp.async.commit_group;");
    }

    for (int s = 0; s < NT; s++) {
        asm volatile("cp.async.wait_group %0;" :: "n"(STAGES - 2));
        __syncthreads();
        int ld = s + STAGES - 1;
        if (ld < NT) loadStage(ld & (STAGES - 1), ld * KT);
        asm volatile("cp.async.commit_group;");

        int st = s & (STAGES - 1);
        #pragma unroll
        for (int ks = 0; ks < 2; ks++) {
            int k0 = ks * 8;
            wmma::fragment<wmma::matrix_a, 16, 16, 8, wmma::precision::tf32, wmma::row_major> af[4];
            wmma::fragment<wmma::matrix_b, 16, 16, 8, wmma::precision::tf32, wmma::row_major> bf[2];
            #pragma unroll
            for (int i = 0; i < 4; i++)
                wmma::load_matrix_sync(af[i], &As[st][wm * 64 + i * 16][k0], 24);
            #pragma unroll
            for (int j = 0; j < 2; j++)
                wmma::load_matrix_sync(bf[j], &Bs[st][k0][wn * 32 + j * 16], 136);
            #pragma unroll
            for (int i = 0; i < 4; i++)
                #pragma unroll
                for (int j = 0; j < 2; j++)
                    wmma::mma_sync(acc[i][j], af[i], bf[j], acc[i][j]);
        }
    }

    #pragma unroll
    for (int i = 0; i < 4; i++) {
        int gr = row0 + wm * 64 + i * 16;
        #pragma unroll
        for (int j = 0; j < 2; j++) {
            int gc = col0 + wn * 32 + j * 16;
            wmma::store_matrix_sync(&d_S[(size_t)gr * SST + gc], acc[i][j], SST, wmma::mem_row_major);
        }
    }
}

// ---------------- copy skip block into d_out ----------------
__global__ void skipcopy_kernel(float* __restrict__ out, int Nn) {
    int idx = blockIdx.x * blockDim.x + threadIdx.x;
    if (idx >= Nn * DD) return;
    int n = idx / DD, c = idx - n * DD;
    out[idx] = d_S[(size_t)n * SST + 900 + c];
}

// ---------------- CSR build ----------------
__global__ void zerodeg_kernel(int Nn) {
    int i = blockIdx.x * blockDim.x + threadIdx.x;
    if (i < Nn) d_deg[i] = 0;
}

__global__ void hist_kernel(const int* __restrict__ EI, int Ee) {
    int e = blockIdx.x * blockDim.x + threadIdx.x;
    if (e < Ee) atomicAdd(&d_deg[EI[Ee + e]], 1);
}

__global__ void scan1_kernel(int Nn) {
    __shared__ int sdata[256];
    int t = threadIdx.x;
    int i = blockIdx.x * 256 + t;
    int v = (i < Nn) ? d_deg[i] : 0;
    sdata[t] = v;
    __syncthreads();
    #pragma unroll
    for (int off = 1; off < 256; off <<= 1) {
        int x = (t >= off) ? sdata[t - off] : 0;
        __syncthreads();
        sdata[t] += x;
        __syncthreads();
    }
    if (i < Nn) d_rowptr[i] = sdata[t] - v;     // in-block exclusive
    if (t == 255) d_blksum[blockIdx.x] = sdata[255];
}

__global__ void scan2_kernel(int NB) {
    __shared__ int sdata[256];
    int t = threadIdx.x;
    int v = (t < NB) ? d_blksum[t] : 0;
    sdata[t] = v;
    __syncthreads();
    #pragma unroll
    for (int off = 1; off < 256; off <<= 1) {
        int x = (t >= off) ? sdata[t - off] : 0;
        __syncthreads();
        sdata[t] += x;
        __syncthreads();
    }
    if (t < NB) d_blksum[t] = sdata[t] - v;     // exclusive block offsets
}

__global__ void scan3_kernel(int Nn) {
    int i = blockIdx.x * blockDim.x + threadIdx.x;
    if (i >= Nn) return;
    int val = d_rowptr[i] + d_blksum[i >> 8];
    d_rowptr[i] = val;
    d_cursor[i] = val;
    if (i == Nn - 1) d_rowptr[Nn] = val + d_deg[i];
}

__global__ void scatter_kernel(const int* __restrict__ EI, int Ee) {
    int e = blockIdx.x * blockDim.x + threadIdx.x;
    if (e >= Ee) return;
    int dst = EI[Ee + e];
    int pos = atomicAdd(&d_cursor[dst], 1);
    d_edges[pos] = make_int2(EI[e], e);
}

// ---------------- fused edge kernel: one warp per destination node ----------------
__global__ void __launch_bounds__(256) edgeF_kernel(const float* __restrict__ EA,
                                                    const float* __restrict__ Wcls,
                                                    const float* __restrict__ bcls,
                                                    float* __restrict__ out, int Nn) {
    __shared__ float sWcls[DD * 5];
    __shared__ float sG[8 * DD];
    __shared__ float sW2[2 * DD];
    __shared__ float sBcls[5];
    for (int i = threadIdx.x; i < DD * 5; i += 256) sWcls[i] = Wcls[i];
    for (int i = threadIdx.x; i < 8 * DD; i += 256) sG[i] = d_G8[i];
    for (int i = threadIdx.x; i < 2 * DD; i += 256) sW2[i] = d_W2f[i];
    if (threadIdx.x < 5) sBcls[threadIdx.x] = bcls[threadIdx.x];
    __syncthreads();

    int lane = threadIdx.x & 31;
    int n = blockIdx.x * 8 + (threadIdx.x >> 5);
    if (n >= Nn) return;

    int beg = d_rowptr[n], end = d_rowptr[n + 1];
    const float* rowD = d_S + (size_t)n * SST;

    // lane owns chunks {lane, lane+32, lane+64} (cols = 4*chunk .. +3); valid if chunk < 75
    float4 q[3], cd[3], acc[3];
    #pragma unroll
    for (int j = 0; j < 3; j++) {
        int ch = lane + 32 * j;
        if (ch < 75) {
            q[j]  = __ldg((const float4*)&rowD[4 * ch]);
            cd[j] = __ldg((const float4*)&rowD[1200 + 4 * ch]);
        } else {
            q[j] = make_float4(0, 0, 0, 0);
            cd[j] = make_float4(0, 0, 0, 0);
        }
        acc[j] = make_float4(0, 0, 0, 0);
    }
    float den0 = 0, den1 = 0, den2 = 0, den3 = 0;

    for (int p = beg; p < end; p++) {
        int2 se = __ldg(&d_edges[p]);
        int src = se.x, e = se.y;
        const float* rowS = d_S + (size_t)src * SST;
        float4 ea = __ldg((const float4*)&EA[4 * e]);

        float4 k4[3], cs4[3], v4[3];
        #pragma unroll
        for (int j = 0; j < 3; j++) {
            int ch = lane + 32 * j;
            if (ch < 75) {
                k4[j]  = __ldg((const float4*)&rowS[300 + 4 * ch]);
                cs4[j] = __ldg((const float4*)&rowS[1500 + 4 * ch]);
                v4[j]  = __ldg((const float4*)&rowS[600 + 4 * ch]);
            } else {
                k4[j] = make_float4(0, 0, 0, 0);
                cs4[j] = make_float4(0, 0, 0, 0);
                v4[j] = make_float4(0, 0, 0, 0);
            }
        }

        // ---- logits over 5 classes ----
        float l0 = 0, l1 = 0, l2 = 0, l3 = 0, l4 = 0;
        #pragma unroll
        for (int j = 0; j < 3; j++) {
            int ch = lane + 32 * j;
            if (ch >= 75) continue;
            int c = 4 * ch;
            #pragma unroll
            for (int i = 0; i < 4; i++) {
                int col = c + i;
                float h = fast_tanh((&cd[j].x)[i] + (&cs4[j].x)[i]
                                    + ea.z * sW2[col] + ea.w * sW2[DD + col]);
                const float* wc = sWcls + col * 5;
                l0 = fmaf(h, wc[0], l0); l1 = fmaf(h, wc[1], l1); l2 = fmaf(h, wc[2], l2);
                l3 = fmaf(h, wc[3], l3); l4 = fmaf(h, wc[4], l4);
            }
        }
        #pragma unroll
        for (int o = 16; o; o >>= 1) {
            l0 += __shfl_xor_sync(0xffffffffu, l0, o);
            l1 += __shfl_xor_sync(0xffffffffu, l1, o);
            l2 += __shfl_xor_sync(0xffffffffu, l2, o);
            l3 += __shfl_xor_sync(0xffffffffu, l3, o);
            l4 += __shfl_xor_sync(0xffffffffu, l4, o);
        }
        l0 += sBcls[0]; l1 += sBcls[1]; l2 += sBcls[2]; l3 += sBcls[3]; l4 += sBcls[4];
        float m = fmaxf(fmaxf(fmaxf(l0, l1), fmaxf(l2, l3)), l4);
        float p0 = __expf(l0 - m), p1 = __expf(l1 - m), p2 = __expf(l2 - m);
        float p3 = __expf(l3 - m), p4 = __expf(l4 - m);
        float inv = 1.0f / (p0 + p1 + p2 + p3 + p4);
        p0 *= inv; p1 *= inv; p2 *= inv; p3 *= inv; p4 *= inv;
        float t0 = ea.x > 0.0f ? 1.0f : 0.0f;
        float t1 = ea.y < 0.0f ? 1.0f : 0.0f;

        // ---- ef and alpha ----
        float4 ef[3];
        float a0 = 0, a1 = 0, a2 = 0, a3 = 0;
        #pragma unroll
        for (int j = 0; j < 3; j++) {
            int ch = lane + 32 * j;
            ef[j] = make_float4(0, 0, 0, 0);
            if (ch >= 75) continue;
            int c = 4 * ch;
            #pragma unroll
            for (int i = 0; i < 4; i++) {
                int col = c + i;
                float efv = sG[2100 + col];
                efv = fmaf(p0, sG[col], efv);
                efv = fmaf(p1, sG[300 + col], efv);
                efv = fmaf(p2, sG[600 + col], efv);
                efv = fmaf(p3, sG[900 + col], efv);
                efv = fmaf(p4, sG[1200 + col], efv);
                efv = fmaf(t0, sG[1500 + col], efv);
                efv = fmaf(t1, sG[1800 + col], efv);
                (&ef[j].x)[i] = efv;
                float pr = (&q[j].x)[i] * ((&k4[j].x)[i] + efv);
                if (col < 75) a0 += pr;
                else if (col < 150) a1 += pr;
                else if (col < 225) a2 += pr;
                else a3 += pr;
            }
        }
        #pragma unroll
        for (int o = 16; o; o >>= 1) {
            a0 += __shfl_xor_sync(0xffffffffu, a0, o);
            a1 += __shfl_xor_sync(0xffffffffu, a1, o);
            a2 += __shfl_xor_sync(0xffffffffu, a2, o);
            a3 += __shfl_xor_sync(0xffffffffu, a3, o);
        }
        const float sc = 0.115470053837925152f;  // 1/sqrt(75)
        float w0 = __expf(a0 * sc), w1 = __expf(a1 * sc);
        float w2 = __expf(a2 * sc), w3 = __expf(a3 * sc);
        den0 += w0; den1 += w1; den2 += w2; den3 += w3;

        // ---- accumulate unnormalized message ----
        #pragma unroll
        for (int j = 0; j < 3; j++) {
            int ch = lane + 32 * j;
            if (ch >= 75) continue;
            int c = 4 * ch;
            #pragma unroll
            for (int i = 0; i < 4; i++) {
                int col = c + i;
                float w = col < 75 ? w0 : (col < 150 ? w1 : (col < 225 ? w2 : w3));
                (&acc[j].x)[i] = fmaf(w, (&v4[j].x)[i] + (&ef[j].x)[i], (&acc[j].x)[i]);
            }
        }
    }

    // ---- finalize: out += acc / den (out already holds skip) ----
    float i0 = den0 > 0 ? __fdividef(1.0f, den0) : 0.0f;
    float i1 = den1 > 0 ? __fdividef(1.0f, den1) : 0.0f;
    float i2 = den2 > 0 ? __fdividef(1.0f, den2) : 0.0f;
    float i3 = den3 > 0 ? __fdividef(1.0f, den3) : 0.0f;
    #pragma unroll
    for (int j = 0; j < 3; j++) {
        int ch = lane + 32 * j;
        if (ch >= 75) continue;
        int c = 4 * ch;
        float4 o4 = *(float4*)&out[(size_t)n * DD + c];
        #pragma unroll
        for (int i = 0; i < 4; i++) {
            int col = c + i;
            float iv = col < 75 ? i0 : (col < 150 ? i1 : (col < 225 ? i2 : i3));
            (&o4.x)[i] = fmaf((&acc[j].x)[i], iv, (&o4.x)[i]);
        }
        *(float4*)&out[(size_t)n * DD + c] = o4;
    }
}

// ---------------- host launcher ----------------
extern "C" void kernel_launch(void* const* d_in, const int* in_sizes, int n_in,
                              void* d_out, int out_size) {
    const float* x     = (const float*)d_in[0];
    const int*   EI    = (const int*)d_in[1];
    const float* EA    = (const float*)d_in[2];
    const float* nrm   = (const float*)d_in[3];
    const float* Wq    = (const float*)d_in[4];
    const float* bq    = (const float*)d_in[5];
    const float* Wk    = (const float*)d_in[6];
    const float* bk    = (const float*)d_in[7];
    const float* Wv    = (const float*)d_in[8];
    const float* bv    = (const float*)d_in[9];
    const float* We    = (const float*)d_in[10];
    const float* Wn    = (const float*)d_in[11];
    const float* bn    = (const float*)d_in[12];
    const float* Wxy   = (const float*)d_in[13];
    const float* bxy   = (const float*)d_in[14];
    const float* Wloc  = (const float*)d_in[15];
    const float* bloc  = (const float*)d_in[16];
    const float* Wobj  = (const float*)d_in[17];
    const float* bobj  = (const float*)d_in[18];
    const float* Wfus  = (const float*)d_in[19];
    const float* bfus  = (const float*)d_in[20];
    const float* Wcls  = (const float*)d_in[21];
    const float* bcls  = (const float*)d_in[22];
    const float* Wskip = (const float*)d_in[23];
    const float* bskip = (const float*)d_in[24];

    int Nn = in_sizes[0] / DD;
    int Ee = in_sizes[1] / 2;
    float* out = (float*)d_out;

    static bool attr_set = false;
    const int smem_bytes = STAGES * (128 * 24 + 16 * 136) * 4;  // 83968
    if (!attr_set) {
        cudaFuncSetAttribute(gemm_tf32_kernel, cudaFuncAttributeMaxDynamicSharedMemorySize, smem_bytes);
        attr_set = true;
    }

    fold1_kernel<<<(DD + 127) / 128, 128>>>(Wn, Wxy, Wloc, Wfus, (const float*)d_in[25], bxy, bn, bobj, bloc, bfus);
    fold2_kernel<<<(DD + 127) / 128, 128>>>(We);
    buildA_kernel<<<(Nn * KK + 255) / 256, 256>>>(x, nrm, Nn);
    buildW_kernel<<<(KK * WST + 255) / 256, 256>>>(Wq, Wk, Wv, Wskip, Wobj, bq, bk, bv, bskip);

    dim3 gg(WST / 128, MPAD / 128);  // 15 x 391
    gemm_tf32_kernel<<<gg, 256, smem_bytes>>>();

    skipcopy_kernel<<<(Nn * DD + 255) / 256, 256>>>(out, Nn);

    // CSR build
    int NB = (Nn + 255) / 256;
    zerodeg_kernel<<<NB, 256>>>(Nn);
    hist_kernel<<<(Ee + 255) / 256, 256>>>(EI, Ee);
    scan1_kernel<<<NB, 256>>>(Nn);
    scan2_kernel<<<1, 256>>>(NB);
    scan3_kernel<<<NB, 256>>>(Nn);
    scatter_kernel<<<(Ee + 255) / 256, 256>>>(EI, Ee);

    edgeF_kernel<<<(Nn + 7) / 8, 256>>>(EA, Wcls, bcls, out, Nn);
}

// round 7
// speedup vs baseline: 1.8689x; 1.4549x over previous
#include <cuda_runtime.h>
#include <cuda_fp16.h>
#include <mma.h>
#include <math.h>
#include <stdint.h>

using namespace nvcuda;

#define DD 300
#define NCOLS 1800
#define KK2 320             // K padded to 320 (zero-padded)
#define MAXN 50000
#define MAXE 250000
#define MPAD 50048          // 391 * 128
#define SST  1920           // padded row stride of d_S
#define STAGES 4
#define KT 32
#define NT (KK2 / KT)       // 10

// ---- static scratch (allocation-free rule: __device__ globals) ----
__device__ __half d_Ah[(size_t)MPAD * KK2];    // [MPAD][320] fp16, pads stay 0
__device__ __half d_WhT[(size_t)SST * KK2];    // [1920][320] = Wbig transposed, fp16
__device__ float  d_S[(size_t)MPAD * SST];     // [N][1920] = Q|K|V|skip|Cd|Cs
__device__ float  d_NLi[3 * DD];
__device__ float  d_NLj[3 * DD];
__device__ float  d_W2f[2 * DD];
__device__ float  d_c0[DD];
__device__ float  d_T8[8 * DD];
__device__ float  d_G8[8 * DD];
// CSR scratch
__device__ int  d_deg[MAXN];
__device__ int  d_rowptr[MAXN + 1];
__device__ int  d_cursor[MAXN];
__device__ int  d_blksum[256];
__device__ int2 d_edges[MAXE];

__device__ __forceinline__ float fast_tanh(float x) {
    float r;
    asm("tanh.approx.f32 %0, %1;" : "=f"(r) : "f"(x));
    return r;
}

// ---------------- fold 1 ----------------
__global__ void fold1_kernel(const float* __restrict__ Wn, const float* __restrict__ Wxy,
                             const float* __restrict__ Wloc, const float* __restrict__ Wfus,
                             const float* __restrict__ vocab, const float* __restrict__ bxy,
                             const float* __restrict__ bn, const float* __restrict__ bobj,
                             const float* __restrict__ bloc, const float* __restrict__ bfus) {
    int c = blockIdx.x * blockDim.x + threadIdx.x;
    if (c >= DD) return;
    float nli0 = 0, nli1 = 0, nli2 = 0, nlj0 = 0, nlj1 = 0, nlj2 = 0;
    float w20 = 0, w21 = 0, c0 = 0;
    float t0 = 0, t1 = 0, t2 = 0, t3 = 0, t4 = 0, t5 = 0, t6 = 0;
    for (int k = 0; k < DD; k++) {
        float wl0 = Wloc[k * DD + c];
        float wl1 = Wloc[(DD + k) * DD + c];
        float wl2 = Wloc[(2 * DD + k) * DD + c];
        float wn0 = Wn[k], wn1 = Wn[DD + k], wn2 = Wn[2 * DD + k];
        nli0 = fmaf(wn0, wl1, nli0); nli1 = fmaf(wn1, wl1, nli1); nli2 = fmaf(wn2, wl1, nli2);
        nlj0 = fmaf(wn0, wl2, nlj0); nlj1 = fmaf(wn1, wl2, nlj1); nlj2 = fmaf(wn2, wl2, nlj2);
        w20 = fmaf(Wxy[k], wl0, w20); w21 = fmaf(Wxy[DD + k], wl0, w21);
        c0 = fmaf(bxy[k], wl0, c0);
        c0 = fmaf(bn[k], wl1 + wl2, c0);
        float wf0 = Wfus[k * DD + c];
        float wf1 = Wfus[(DD + k) * DD + c];
        t0 = fmaf(vocab[2 * DD + k], wf1, t0);
        t1 = fmaf(vocab[3 * DD + k], wf1, t1);
        t2 = fmaf(vocab[4 * DD + k], wf1, t2);
        t3 = fmaf(vocab[5 * DD + k], wf1, t3);
        t4 = fmaf(vocab[6 * DD + k], wf1, t4);
        t5 = fmaf(vocab[k], wf0, t5);
        t6 = fmaf(vocab[DD + k], wf0, t6);
    }
    d_NLi[0 * DD + c] = nli0; d_NLi[1 * DD + c] = nli1; d_NLi[2 * DD + c] = nli2;
    d_NLj[0 * DD + c] = nlj0; d_NLj[1 * DD + c] = nlj1; d_NLj[2 * DD + c] = nlj2;
    d_W2f[c] = w20; d_W2f[DD + c] = w21;
    d_c0[c] = c0 + bobj[c] + bloc[c];
    d_T8[0 * DD + c] = t0; d_T8[1 * DD + c] = t1; d_T8[2 * DD + c] = t2;
    d_T8[3 * DD + c] = t3; d_T8[4 * DD + c] = t4; d_T8[5 * DD + c] = t5;
    d_T8[6 * DD + c] = t6; d_T8[7 * DD + c] = bfus[c];
}

// ---------------- fold 2: G8 = T8 @ We ----------------
__global__ void fold2_kernel(const float* __restrict__ We) {
    int c = blockIdx.x * blockDim.x + threadIdx.x;
    if (c >= DD) return;
    float g[8] = {0, 0, 0, 0, 0, 0, 0, 0};
    for (int k = 0; k < DD; k++) {
        float w = We[k * DD + c];
        #pragma unroll
        for (int j = 0; j < 8; j++) g[j] = fmaf(d_T8[j * DD + k], w, g[j]);
    }
    #pragma unroll
    for (int j = 0; j < 8; j++) d_G8[j * DD + c] = g[j];
}

// ---------------- build A (fp16; pad entries never written, stay zero) ----------------
__global__ void buildA_kernel(const float* __restrict__ x, const float* __restrict__ nrm, int Nn) {
    int idx = blockIdx.x * blockDim.x + threadIdx.x;
    if (idx >= Nn * 304) return;
    int n = idx / 304, k = idx - n * 304;
    float v;
    if (k < DD) v = x[n * DD + k];
    else if (k < DD + 3) v = nrm[n * 3 + (k - DD)];
    else v = 1.0f;
    d_Ah[(size_t)n * KK2 + k] = __float2half_rn(v);
}

// ---------------- build WhT [c][k] fp16 ----------------
__global__ void buildW_kernel(const float* __restrict__ Wq, const float* __restrict__ Wk,
                              const float* __restrict__ Wv, const float* __restrict__ Wskip,
                              const float* __restrict__ Wobj, const float* __restrict__ bq,
                              const float* __restrict__ bk, const float* __restrict__ bv,
                              const float* __restrict__ bskip) {
    int idx = blockIdx.x * blockDim.x + threadIdx.x;
    if (idx >= NCOLS * 304) return;
    int c = idx / 304, k = idx - c * 304;
    int b = c / DD, cc = c - b * DD;
    float v = 0.0f;
    if (k < DD) {
        if (b == 0) v = Wq[k * DD + cc];
        else if (b == 1) v = Wk[k * DD + cc];
        else if (b == 2) v = Wv[k * DD + cc];
        else if (b == 3) v = Wskip[k * DD + cc];
        else if (b == 4) v = Wobj[k * DD + cc] - Wobj[(DD + k) * DD + cc];
        else v = Wobj[(DD + k) * DD + cc];
    } else if (k < DD + 3) {
        int r = k - DD;
        if (b == 4) v = d_NLi[r * DD + cc];
        else if (b == 5) v = d_NLj[r * DD + cc];
    } else {
        if (b == 0) v = bq[cc];
        else if (b == 1) v = bk[cc];
        else if (b == 2) v = bv[cc];
        else if (b == 3) v = bskip[cc];
        else if (b == 4) v = d_c0[cc];
    }
    d_WhT[(size_t)c * KK2 + k] = __float2half_rn(v);
}

// ---------------- node GEMM (fp16 wmma m16n16k16, cp.async 4-stage) ----------------
// Tile 128x128, warp tile 64x32. A row-major [m][k], B from WhT[n][k] -> col_major frags.
__global__ void __launch_bounds__(256, 2) gemm_fp16_kernel() {
    extern __shared__ __half sm[];
    __half (*As)[128][40] = (__half (*)[128][40])sm;                         // STAGES x 128 x 40
    __half (*Bs)[128][40] = (__half (*)[128][40])(sm + STAGES * 128 * 40);   // STAGES x 128 x 40

    int tid = threadIdx.x;
    int wid = tid >> 5;
    int wm = wid >> 2;            // 0..1
    int wn = wid & 3;             // 0..3
    int row0 = blockIdx.y * 128, col0 = blockIdx.x * 128;

    // loader: idx 0..511 -> row = idx>>2, seg = idx&3 (8 halves = 16B per chunk)
    int lrow = tid >> 1;              // for u-loop below we use idx = tid + 256u
    (void)lrow;

    wmma::fragment<wmma::accumulator, 16, 16, 16, float> acc[4][2];
    #pragma unroll
    for (int i = 0; i < 4; i++)
        #pragma unroll
        for (int j = 0; j < 2; j++) wmma::fill_fragment(acc[i][j], 0.0f);

    auto loadStage = [&](int st, int kt) {
        #pragma unroll
        for (int u = 0; u < 2; u++) {
            int idx = tid + 256 * u;       // 0..511
            int row = idx >> 2, seg = idx & 3;
            const __half* ga = &d_Ah[(size_t)(row0 + row) * KK2 + kt + seg * 8];
            uint32_t da = (uint32_t)__cvta_generic_to_shared(&As[st][row][seg * 8]);
            asm volatile("cp.async.cg.shared.global [%0], [%1], 16;" :: "r"(da), "l"(ga));
            const __half* gb = &d_WhT[(size_t)(col0 + row) * KK2 + kt + seg * 8];
            uint32_t db = (uint32_t)__cvta_generic_to_shared(&Bs[st][row][seg * 8]);
            asm volatile("cp.async.cg.shared.global [%0], [%1], 16;" :: "r"(db), "l"(gb));
        }
    };

    #pragma unroll
    for (int i = 0; i < STAGES - 1; i++) {
        loadStage(i, i * KT);
        asm volatile("cp.async.commit_group;");
    }

    for (int s = 0; s < NT; s++) {
        asm volatile("cp.async.wait_group %0;" :: "n"(STAGES - 2));
        __syncthreads();
        int ld = s + STAGES - 1;
        if (ld < NT) loadStage(ld & (STAGES - 1), ld * KT);
        asm volatile("cp.async.commit_group;");

        int st = s & (STAGES - 1);
        #pragma unroll
        for (int ks = 0; ks < 2; ks++) {
            int k0 = ks * 16;
            wmma::fragment<wmma::matrix_b, 16, 16, 16, __half, wmma::col_major> bf[2];
            #pragma unroll
            for (int j = 0; j < 2; j++)
                wmma::load_matrix_sync(bf[j], &Bs[st][wn * 32 + j * 16][k0], 40);
            #pragma unroll
            for (int i = 0; i < 4; i++) {
                wmma::fragment<wmma::matrix_a, 16, 16, 16, __half, wmma::row_major> af;
                wmma::load_matrix_sync(af, &As[st][wm * 64 + i * 16][k0], 40);
                #pragma unroll
                for (int j = 0; j < 2; j++)
                    wmma::mma_sync(acc[i][j], af, bf[j], acc[i][j]);
            }
        }
    }

    #pragma unroll
    for (int i = 0; i < 4; i++) {
        int gr = row0 + wm * 64 + i * 16;
        #pragma unroll
        for (int j = 0; j < 2; j++) {
            int gc = col0 + wn * 32 + j * 16;
            wmma::store_matrix_sync(&d_S[(size_t)gr * SST + gc], acc[i][j], SST, wmma::mem_row_major);
        }
    }
}

// ---------------- copy skip block into d_out ----------------
__global__ void skipcopy_kernel(float* __restrict__ out, int Nn) {
    int idx = blockIdx.x * blockDim.x + threadIdx.x;
    if (idx >= Nn * DD) return;
    int n = idx / DD, c = idx - n * DD;
    out[idx] = d_S[(size_t)n * SST + 900 + c];
}

// ---------------- CSR build ----------------
__global__ void zerodeg_kernel(int Nn) {
    int i = blockIdx.x * blockDim.x + threadIdx.x;
    if (i < Nn) d_deg[i] = 0;
}
__global__ void hist_kernel(const int* __restrict__ EI, int Ee) {
    int e = blockIdx.x * blockDim.x + threadIdx.x;
    if (e < Ee) atomicAdd(&d_deg[EI[Ee + e]], 1);
}
__global__ void scan1_kernel(int Nn) {
    __shared__ int sdata[256];
    int t = threadIdx.x;
    int i = blockIdx.x * 256 + t;
    int v = (i < Nn) ? d_deg[i] : 0;
    sdata[t] = v;
    __syncthreads();
    #pragma unroll
    for (int off = 1; off < 256; off <<= 1) {
        int x = (t >= off) ? sdata[t - off] : 0;
        __syncthreads();
        sdata[t] += x;
        __syncthreads();
    }
    if (i < Nn) d_rowptr[i] = sdata[t] - v;
    if (t == 255) d_blksum[blockIdx.x] = sdata[255];
}
__global__ void scan2_kernel(int NB) {
    __shared__ int sdata[256];
    int t = threadIdx.x;
    int v = (t < NB) ? d_blksum[t] : 0;
    sdata[t] = v;
    __syncthreads();
    #pragma unroll
    for (int off = 1; off < 256; off <<= 1) {
        int x = (t >= off) ? sdata[t - off] : 0;
        __syncthreads();
        sdata[t] += x;
        __syncthreads();
    }
    if (t < NB) d_blksum[t] = sdata[t] - v;
}
__global__ void scan3_kernel(int Nn) {
    int i = blockIdx.x * blockDim.x + threadIdx.x;
    if (i >= Nn) return;
    int val = d_rowptr[i] + d_blksum[i >> 8];
    d_rowptr[i] = val;
    d_cursor[i] = val;
    if (i == Nn - 1) d_rowptr[Nn] = val + d_deg[i];
}
__global__ void scatter_kernel(const int* __restrict__ EI, int Ee) {
    int e = blockIdx.x * blockDim.x + threadIdx.x;
    if (e >= Ee) return;
    int dst = EI[Ee + e];
    int pos = atomicAdd(&d_cursor[dst], 1);
    d_edges[pos] = make_int2(EI[e], e);
}

// ---------------- fused edge kernel: one warp per destination node ----------------
__global__ void __launch_bounds__(256) edgeF_kernel(const float* __restrict__ EA,
                                                    const float* __restrict__ Wcls,
                                                    const float* __restrict__ bcls,
                                                    float* __restrict__ out, int Nn) {
    __shared__ float sWcls[DD * 5];
    __shared__ float sG[8 * DD];
    __shared__ float sW2[2 * DD];
    __shared__ float sBcls[5];
    for (int i = threadIdx.x; i < DD * 5; i += 256) sWcls[i] = Wcls[i];
    for (int i = threadIdx.x; i < 8 * DD; i += 256) sG[i] = d_G8[i];
    for (int i = threadIdx.x; i < 2 * DD; i += 256) sW2[i] = d_W2f[i];
    if (threadIdx.x < 5) sBcls[threadIdx.x] = bcls[threadIdx.x];
    __syncthreads();

    int lane = threadIdx.x & 31;
    int n = blockIdx.x * 8 + (threadIdx.x >> 5);
    if (n >= Nn) return;

    int beg = d_rowptr[n], end = d_rowptr[n + 1];
    const float* rowD = d_S + (size_t)n * SST;

    float4 q[3], cd[3], acc[3];
    #pragma unroll
    for (int j = 0; j < 3; j++) {
        int ch = lane + 32 * j;
        if (ch < 75) {
            q[j]  = __ldg((const float4*)&rowD[4 * ch]);
            cd[j] = __ldg((const float4*)&rowD[1200 + 4 * ch]);
        } else {
            q[j] = make_float4(0, 0, 0, 0);
            cd[j] = make_float4(0, 0, 0, 0);
        }
        acc[j] = make_float4(0, 0, 0, 0);
    }
    float den0 = 0, den1 = 0, den2 = 0, den3 = 0;

    for (int p = beg; p < end; p++) {
        int2 se = __ldg(&d_edges[p]);
        int src = se.x, e = se.y;
        const float* rowS = d_S + (size_t)src * SST;
        float4 ea = __ldg((const float4*)&EA[4 * e]);

        float4 k4[3], cs4[3], v4[3];
        #pragma unroll
        for (int j = 0; j < 3; j++) {
            int ch = lane + 32 * j;
            if (ch < 75) {
                k4[j]  = __ldg((const float4*)&rowS[300 + 4 * ch]);
                cs4[j] = __ldg((const float4*)&rowS[1500 + 4 * ch]);
                v4[j]  = __ldg((const float4*)&rowS[600 + 4 * ch]);
            } else {
                k4[j] = make_float4(0, 0, 0, 0);
                cs4[j] = make_float4(0, 0, 0, 0);
                v4[j] = make_float4(0, 0, 0, 0);
            }
        }

        float l0 = 0, l1 = 0, l2 = 0, l3 = 0, l4 = 0;
        #pragma unroll
        for (int j = 0; j < 3; j++) {
            int ch = lane + 32 * j;
            if (ch >= 75) continue;
            int c = 4 * ch;
            #pragma unroll
            for (int i = 0; i < 4; i++) {
                int col = c + i;
                float h = fast_tanh((&cd[j].x)[i] + (&cs4[j].x)[i]
                                    + ea.z * sW2[col] + ea.w * sW2[DD + col]);
                const float* wc = sWcls + col * 5;
                l0 = fmaf(h, wc[0], l0); l1 = fmaf(h, wc[1], l1); l2 = fmaf(h, wc[2], l2);
                l3 = fmaf(h, wc[3], l3); l4 = fmaf(h, wc[4], l4);
            }
        }
        #pragma unroll
        for (int o = 16; o; o >>= 1) {
            l0 += __shfl_xor_sync(0xffffffffu, l0, o);
            l1 += __shfl_xor_sync(0xffffffffu, l1, o);
            l2 += __shfl_xor_sync(0xffffffffu, l2, o);
            l3 += __shfl_xor_sync(0xffffffffu, l3, o);
            l4 += __shfl_xor_sync(0xffffffffu, l4, o);
        }
        l0 += sBcls[0]; l1 += sBcls[1]; l2 += sBcls[2]; l3 += sBcls[3]; l4 += sBcls[4];
        float m = fmaxf(fmaxf(fmaxf(l0, l1), fmaxf(l2, l3)), l4);
        float p0 = __expf(l0 - m), p1 = __expf(l1 - m), p2 = __expf(l2 - m);
        float p3 = __expf(l3 - m), p4 = __expf(l4 - m);
        float inv = 1.0f / (p0 + p1 + p2 + p3 + p4);
        p0 *= inv; p1 *= inv; p2 *= inv; p3 *= inv; p4 *= inv;
        float t0 = ea.x > 0.0f ? 1.0f : 0.0f;
        float t1 = ea.y < 0.0f ? 1.0f : 0.0f;

        float4 ef[3];
        float a0 = 0, a1 = 0, a2 = 0, a3 = 0;
        #pragma unroll
        for (int j = 0; j < 3; j++) {
            int ch = lane + 32 * j;
            ef[j] = make_float4(0, 0, 0, 0);
            if (ch >= 75) continue;
            int c = 4 * ch;
            #pragma unroll
            for (int i = 0; i < 4; i++) {
                int col = c + i;
                float efv = sG[2100 + col];
                efv = fmaf(p0, sG[col], efv);
                efv = fmaf(p1, sG[300 + col], efv);
                efv = fmaf(p2, sG[600 + col], efv);
                efv = fmaf(p3, sG[900 + col], efv);
                efv = fmaf(p4, sG[1200 + col], efv);
                efv = fmaf(t0, sG[1500 + col], efv);
                efv = fmaf(t1, sG[1800 + col], efv);
                (&ef[j].x)[i] = efv;
                float pr = (&q[j].x)[i] * ((&k4[j].x)[i] + efv);
                if (col < 75) a0 += pr;
                else if (col < 150) a1 += pr;
                else if (col < 225) a2 += pr;
                else a3 += pr;
            }
        }
        #pragma unroll
        for (int o = 16; o; o >>= 1) {
            a0 += __shfl_xor_sync(0xffffffffu, a0, o);
            a1 += __shfl_xor_sync(0xffffffffu, a1, o);
            a2 += __shfl_xor_sync(0xffffffffu, a2, o);
            a3 += __shfl_xor_sync(0xffffffffu, a3, o);
        }
        const float sc = 0.115470053837925152f;  // 1/sqrt(75)
        float w0 = __expf(a0 * sc), w1 = __expf(a1 * sc);
        float w2 = __expf(a2 * sc), w3 = __expf(a3 * sc);
        den0 += w0; den1 += w1; den2 += w2; den3 += w3;

        #pragma unroll
        for (int j = 0; j < 3; j++) {
            int ch = lane + 32 * j;
            if (ch >= 75) continue;
            int c = 4 * ch;
            #pragma unroll
            for (int i = 0; i < 4; i++) {
                int col = c + i;
                float w = col < 75 ? w0 : (col < 150 ? w1 : (col < 225 ? w2 : w3));
                (&acc[j].x)[i] = fmaf(w, (&v4[j].x)[i] + (&ef[j].x)[i], (&acc[j].x)[i]);
            }
        }
    }

    float i0 = den0 > 0 ? __fdividef(1.0f, den0) : 0.0f;
    float i1 = den1 > 0 ? __fdividef(1.0f, den1) : 0.0f;
    float i2 = den2 > 0 ? __fdividef(1.0f, den2) : 0.0f;
    float i3 = den3 > 0 ? __fdividef(1.0f, den3) : 0.0f;
    #pragma unroll
    for (int j = 0; j < 3; j++) {
        int ch = lane + 32 * j;
        if (ch >= 75) continue;
        int c = 4 * ch;
        float4 o4 = *(float4*)&out[(size_t)n * DD + c];
        #pragma unroll
        for (int i = 0; i < 4; i++) {
            int col = c + i;
            float iv = col < 75 ? i0 : (col < 150 ? i1 : (col < 225 ? i2 : i3));
            (&o4.x)[i] = fmaf((&acc[j].x)[i], iv, (&o4.x)[i]);
        }
        *(float4*)&out[(size_t)n * DD + c] = o4;
    }
}

// ---------------- host launcher ----------------
extern "C" void kernel_launch(void* const* d_in, const int* in_sizes, int n_in,
                              void* d_out, int out_size) {
    const float* x     = (const float*)d_in[0];
    const int*   EI    = (const int*)d_in[1];
    const float* EA    = (const float*)d_in[2];
    const float* nrm   = (const float*)d_in[3];
    const float* Wq    = (const float*)d_in[4];
    const float* bq    = (const float*)d_in[5];
    const float* Wk    = (const float*)d_in[6];
    const float* bk    = (const float*)d_in[7];
    const float* Wv    = (const float*)d_in[8];
    const float* bv    = (const float*)d_in[9];
    const float* We    = (const float*)d_in[10];
    const float* Wn    = (const float*)d_in[11];
    const float* bn    = (const float*)d_in[12];
    const float* Wxy   = (const float*)d_in[13];
    const float* bxy   = (const float*)d_in[14];
    const float* Wloc  = (const float*)d_in[15];
    const float* bloc  = (const float*)d_in[16];
    const float* Wobj  = (const float*)d_in[17];
    const float* bobj  = (const float*)d_in[18];
    const float* Wfus  = (const float*)d_in[19];
    const float* bfus  = (const float*)d_in[20];
    const float* Wcls  = (const float*)d_in[21];
    const float* bcls  = (const float*)d_in[22];
    const float* Wskip = (const float*)d_in[23];
    const float* bskip = (const float*)d_in[24];
    const float* vocab = (const float*)d_in[25];

    int Nn = in_sizes[0] / DD;
    int Ee = in_sizes[1] / 2;
    float* out = (float*)d_out;

    static bool attr_set = false;
    const int gemm_smem = STAGES * (128 * 40 + 128 * 40) * 2;   // 81920 B
    if (!attr_set) {
        cudaFuncSetAttribute(gemm_fp16_kernel, cudaFuncAttributeMaxDynamicSharedMemorySize, gemm_smem);
        attr_set = true;
    }

    fold1_kernel<<<(DD + 127) / 128, 128>>>(Wn, Wxy, Wloc, Wfus, vocab, bxy, bn, bobj, bloc, bfus);
    fold2_kernel<<<(DD + 127) / 128, 128>>>(We);
    buildA_kernel<<<(Nn * 304 + 255) / 256, 256>>>(x, nrm, Nn);
    buildW_kernel<<<(NCOLS * 304 + 255) / 256, 256>>>(Wq, Wk, Wv, Wskip, Wobj, bq, bk, bv, bskip);

    dim3 gg(SST / 128, MPAD / 128);  // 15 x 391
    gemm_fp16_kernel<<<gg, 256, gemm_smem>>>();

    skipcopy_kernel<<<(Nn * DD + 255) / 256, 256>>>(out, Nn);

    int NB = (Nn + 255) / 256;
    zerodeg_kernel<<<NB, 256>>>(Nn);
    hist_kernel<<<(Ee + 255) / 256, 256>>>(EI, Ee);
    scan1_kernel<<<NB, 256>>>(Nn);
    scan2_kernel<<<1, 256>>>(NB);
    scan3_kernel<<<NB, 256>>>(Nn);
    scatter_kernel<<<(Ee + 255) / 256, 256>>>(EI, Ee);

    edgeF_kernel<<<(Nn + 7) / 8, 256>>>(EA, Wcls, bcls, out, Nn);
}

// round 8
// speedup vs baseline: 2.0114x; 1.0763x over previous
#include <cuda_runtime.h>
#include <cuda_fp16.h>
#include <mma.h>
#include <math.h>
#include <stdint.h>

using namespace nvcuda;

#define DD 300
#define NCOLS 1800
#define KK2 320             // K padded to 320 (zero-padded)
#define MAXN 50000
#define MAXE 250000
#define MPAD 50048          // 391 * 128
#define STAGES 4
#define KT 32
#define NT (KK2 / KT)       // 10
#define SFST 608            // d_Sf row stride (floats): Q[0..300), Cd[304..604)
#define SHST 960            // d_Sh row stride (halves): K[0..300), V[320..620), Cs[640..940)

// ---- static scratch (allocation-free rule: __device__ globals) ----
__device__ __half d_Ah[(size_t)MPAD * KK2];    // [MPAD][320] fp16, pads stay 0
__device__ __half d_WhT[(size_t)SFST * 0 + (size_t)1920 * KK2];  // [1920][320] Wbig^T fp16
__device__ float  d_Sf[(size_t)MPAD * SFST];   // fp32: Q | Cd
__device__ __half d_Sh[(size_t)MPAD * SHST];   // fp16: K | V | Cs
__device__ float  d_NLi[3 * DD];
__device__ float  d_NLj[3 * DD];
__device__ float  d_W2f[2 * DD];
__device__ float  d_c0[DD];
__device__ float  d_T8[8 * DD];
__device__ float  d_G8[8 * DD];
// CSR scratch
__device__ int  d_deg[MAXN];
__device__ int  d_rowptr[MAXN + 1];
__device__ int  d_cursor[MAXN];
__device__ int  d_blksum[256];
__device__ int2 d_edges[MAXE];

__device__ __forceinline__ float fast_tanh(float x) {
    float r;
    asm("tanh.approx.f32 %0, %1;" : "=f"(r) : "f"(x));
    return r;
}
__device__ __forceinline__ float4 h4tof4(uint2 u) {
    __half2 a = *(__half2*)&u.x, b = *(__half2*)&u.y;
    float2 fa = __half22float2(a), fb = __half22float2(b);
    return make_float4(fa.x, fa.y, fb.x, fb.y);
}

// ---------------- fold 1 ----------------
__global__ void fold1_kernel(const float* __restrict__ Wn, const float* __restrict__ Wxy,
                             const float* __restrict__ Wloc, const float* __restrict__ Wfus,
                             const float* __restrict__ vocab, const float* __restrict__ bxy,
                             const float* __restrict__ bn, const float* __restrict__ bobj,
                             const float* __restrict__ bloc, const float* __restrict__ bfus) {
    int c = blockIdx.x * blockDim.x + threadIdx.x;
    if (c >= DD) return;
    float nli0 = 0, nli1 = 0, nli2 = 0, nlj0 = 0, nlj1 = 0, nlj2 = 0;
    float w20 = 0, w21 = 0, c0 = 0;
    float t0 = 0, t1 = 0, t2 = 0, t3 = 0, t4 = 0, t5 = 0, t6 = 0;
    for (int k = 0; k < DD; k++) {
        float wl0 = Wloc[k * DD + c];
        float wl1 = Wloc[(DD + k) * DD + c];
        float wl2 = Wloc[(2 * DD + k) * DD + c];
        float wn0 = Wn[k], wn1 = Wn[DD + k], wn2 = Wn[2 * DD + k];
        nli0 = fmaf(wn0, wl1, nli0); nli1 = fmaf(wn1, wl1, nli1); nli2 = fmaf(wn2, wl1, nli2);
        nlj0 = fmaf(wn0, wl2, nlj0); nlj1 = fmaf(wn1, wl2, nlj1); nlj2 = fmaf(wn2, wl2, nlj2);
        w20 = fmaf(Wxy[k], wl0, w20); w21 = fmaf(Wxy[DD + k], wl0, w21);
        c0 = fmaf(bxy[k], wl0, c0);
        c0 = fmaf(bn[k], wl1 + wl2, c0);
        float wf0 = Wfus[k * DD + c];
        float wf1 = Wfus[(DD + k) * DD + c];
        t0 = fmaf(vocab[2 * DD + k], wf1, t0);
        t1 = fmaf(vocab[3 * DD + k], wf1, t1);
        t2 = fmaf(vocab[4 * DD + k], wf1, t2);
        t3 = fmaf(vocab[5 * DD + k], wf1, t3);
        t4 = fmaf(vocab[6 * DD + k], wf1, t4);
        t5 = fmaf(vocab[k], wf0, t5);
        t6 = fmaf(vocab[DD + k], wf0, t6);
    }
    d_NLi[0 * DD + c] = nli0; d_NLi[1 * DD + c] = nli1; d_NLi[2 * DD + c] = nli2;
    d_NLj[0 * DD + c] = nlj0; d_NLj[1 * DD + c] = nlj1; d_NLj[2 * DD + c] = nlj2;
    d_W2f[c] = w20; d_W2f[DD + c] = w21;
    d_c0[c] = c0 + bobj[c] + bloc[c];
    d_T8[0 * DD + c] = t0; d_T8[1 * DD + c] = t1; d_T8[2 * DD + c] = t2;
    d_T8[3 * DD + c] = t3; d_T8[4 * DD + c] = t4; d_T8[5 * DD + c] = t5;
    d_T8[6 * DD + c] = t6; d_T8[7 * DD + c] = bfus[c];
}

// ---------------- fold 2: G8 = T8 @ We ----------------
__global__ void fold2_kernel(const float* __restrict__ We) {
    int c = blockIdx.x * blockDim.x + threadIdx.x;
    if (c >= DD) return;
    float g[8] = {0, 0, 0, 0, 0, 0, 0, 0};
    for (int k = 0; k < DD; k++) {
        float w = We[k * DD + c];
        #pragma unroll
        for (int j = 0; j < 8; j++) g[j] = fmaf(d_T8[j * DD + k], w, g[j]);
    }
    #pragma unroll
    for (int j = 0; j < 8; j++) d_G8[j * DD + c] = g[j];
}

// ---------------- build A (fp16; pad entries never written, stay zero) ----------------
__global__ void buildA_kernel(const float* __restrict__ x, const float* __restrict__ nrm, int Nn) {
    int idx = blockIdx.x * blockDim.x + threadIdx.x;
    if (idx >= Nn * 304) return;
    int n = idx / 304, k = idx - n * 304;
    float v;
    if (k < DD) v = x[n * DD + k];
    else if (k < DD + 3) v = nrm[n * 3 + (k - DD)];
    else v = 1.0f;
    d_Ah[(size_t)n * KK2 + k] = __float2half_rn(v);
}

// ---------------- build WhT [c][k] fp16 ----------------
__global__ void buildW_kernel(const float* __restrict__ Wq, const float* __restrict__ Wk,
                              const float* __restrict__ Wv, const float* __restrict__ Wskip,
                              const float* __restrict__ Wobj, const float* __restrict__ bq,
                              const float* __restrict__ bk, const float* __restrict__ bv,
                              const float* __restrict__ bskip) {
    int idx = blockIdx.x * blockDim.x + threadIdx.x;
    if (idx >= NCOLS * 304) return;
    int c = idx / 304, k = idx - c * 304;
    int b = c / DD, cc = c - b * DD;
    float v = 0.0f;
    if (k < DD) {
        if (b == 0) v = Wq[k * DD + cc];
        else if (b == 1) v = Wk[k * DD + cc];
        else if (b == 2) v = Wv[k * DD + cc];
        else if (b == 3) v = Wskip[k * DD + cc];
        else if (b == 4) v = Wobj[k * DD + cc] - Wobj[(DD + k) * DD + cc];
        else v = Wobj[(DD + k) * DD + cc];
    } else if (k < DD + 3) {
        int r = k - DD;
        if (b == 4) v = d_NLi[r * DD + cc];
        else if (b == 5) v = d_NLj[r * DD + cc];
    } else {
        if (b == 0) v = bq[cc];
        else if (b == 1) v = bk[cc];
        else if (b == 2) v = bv[cc];
        else if (b == 3) v = bskip[cc];
        else if (b == 4) v = d_c0[cc];
    }
    d_WhT[(size_t)c * KK2 + k] = __float2half_rn(v);
}

// ---------------- node GEMM (fp16 wmma m16n16k16, cp.async 4-stage, routed epilogue) ----
__global__ void __launch_bounds__(256, 2) gemm_fp16_kernel(float* __restrict__ out, int Nn) {
    extern __shared__ __half sm[];
    __half (*As)[128][40] = (__half (*)[128][40])sm;                         // STAGES x 128 x 40
    __half (*Bs)[128][40] = (__half (*)[128][40])(sm + STAGES * 128 * 40);   // STAGES x 128 x 40
    float (*stage)[132] = (float (*)[132])sm;                                // epilogue reuse

    int tid = threadIdx.x;
    int wid = tid >> 5;
    int wm = wid >> 2;            // 0..1
    int wn = wid & 3;             // 0..3
    int row0 = blockIdx.y * 128, col0 = blockIdx.x * 128;

    wmma::fragment<wmma::accumulator, 16, 16, 16, float> acc[4][2];
    #pragma unroll
    for (int i = 0; i < 4; i++)
        #pragma unroll
        for (int j = 0; j < 2; j++) wmma::fill_fragment(acc[i][j], 0.0f);

    auto loadStage = [&](int st, int kt) {
        #pragma unroll
        for (int u = 0; u < 2; u++) {
            int idx = tid + 256 * u;       // 0..511
            int row = idx >> 2, seg = idx & 3;
            const __half* ga = &d_Ah[(size_t)(row0 + row) * KK2 + kt + seg * 8];
            uint32_t da = (uint32_t)__cvta_generic_to_shared(&As[st][row][seg * 8]);
            asm volatile("cp.async.cg.shared.global [%0], [%1], 16;" :: "r"(da), "l"(ga));
            const __half* gb = &d_WhT[(size_t)(col0 + row) * KK2 + kt + seg * 8];
            uint32_t db = (uint32_t)__cvta_generic_to_shared(&Bs[st][row][seg * 8]);
            asm volatile("cp.async.cg.shared.global [%0], [%1], 16;" :: "r"(db), "l"(gb));
        }
    };

    #pragma unroll
    for (int i = 0; i < STAGES - 1; i++) {
        loadStage(i, i * KT);
        asm volatile("cp.async.commit_group;");
    }

    for (int s = 0; s < NT; s++) {
        asm volatile("cp.async.wait_group %0;" :: "n"(STAGES - 2));
        __syncthreads();
        int ld = s + STAGES - 1;
        if (ld < NT) loadStage(ld & (STAGES - 1), ld * KT);
        asm volatile("cp.async.commit_group;");

        int st = s & (STAGES - 1);
        #pragma unroll
        for (int ks = 0; ks < 2; ks++) {
            int k0 = ks * 16;
            wmma::fragment<wmma::matrix_b, 16, 16, 16, __half, wmma::col_major> bf[2];
            #pragma unroll
            for (int j = 0; j < 2; j++)
                wmma::load_matrix_sync(bf[j], &Bs[st][wn * 32 + j * 16][k0], 40);
            #pragma unroll
            for (int i = 0; i < 4; i++) {
                wmma::fragment<wmma::matrix_a, 16, 16, 16, __half, wmma::row_major> af;
                wmma::load_matrix_sync(af, &As[st][wm * 64 + i * 16][k0], 40);
                #pragma unroll
                for (int j = 0; j < 2; j++)
                    wmma::mma_sync(acc[i][j], af, bf[j], acc[i][j]);
            }
        }
    }

    // ---- routed epilogue: stage in smem, then write per logical block ----
    asm volatile("cp.async.wait_group 0;");
    __syncthreads();      // all MMA consumers done with As/Bs
    #pragma unroll
    for (int i = 0; i < 4; i++)
        #pragma unroll
        for (int j = 0; j < 2; j++)
            wmma::store_matrix_sync(&stage[wm * 64 + i * 16][wn * 32 + j * 16],
                                    acc[i][j], 132, wmma::mem_row_major);
    __syncthreads();

    #pragma unroll
    for (int it = 0; it < 16; it++) {
        int idx = tid + it * 256;          // 0..4095  (128 rows x 32 groups)
        int r = idx >> 5;
        int c4 = (idx & 31) * 4;
        int gc = col0 + c4;
        if (gc >= NCOLS) continue;
        int n = row0 + r;
        float4 v = *(float4*)&stage[r][c4];
        int b = gc / DD;
        int cc = gc - b * DD;
        if (b == 0) {
            *(float4*)&d_Sf[(size_t)n * SFST + cc] = v;
        } else if (b == 4) {
            *(float4*)&d_Sf[(size_t)n * SFST + 304 + cc] = v;
        } else if (b == 3) {
            if (n < Nn) *(float4*)&out[(size_t)n * DD + cc] = v;
        } else {
            int off = (b == 1) ? 0 : (b == 2 ? 320 : 640);   // K, V, Cs
            __half2 h0 = __floats2half2_rn(v.x, v.y);
            __half2 h1 = __floats2half2_rn(v.z, v.w);
            uint2 u = make_uint2(*(uint32_t*)&h0, *(uint32_t*)&h1);
            *(uint2*)&d_Sh[(size_t)n * SHST + off + cc] = u;
        }
    }
}

// ---------------- CSR build ----------------
__global__ void zerodeg_kernel(int Nn) {
    int i = blockIdx.x * blockDim.x + threadIdx.x;
    if (i < Nn) d_deg[i] = 0;
}
__global__ void hist_kernel(const int* __restrict__ EI, int Ee) {
    int e = blockIdx.x * blockDim.x + threadIdx.x;
    if (e < Ee) atomicAdd(&d_deg[EI[Ee + e]], 1);
}
__global__ void scan1_kernel(int Nn) {
    __shared__ int sdata[256];
    int t = threadIdx.x;
    int i = blockIdx.x * 256 + t;
    int v = (i < Nn) ? d_deg[i] : 0;
    sdata[t] = v;
    __syncthreads();
    #pragma unroll
    for (int off = 1; off < 256; off <<= 1) {
        int x = (t >= off) ? sdata[t - off] : 0;
        __syncthreads();
        sdata[t] += x;
        __syncthreads();
    }
    if (i < Nn) d_rowptr[i] = sdata[t] - v;
    if (t == 255) d_blksum[blockIdx.x] = sdata[255];
}
__global__ void scan2_kernel(int NB) {
    __shared__ int sdata[256];
    int t = threadIdx.x;
    int v = (t < NB) ? d_blksum[t] : 0;
    sdata[t] = v;
    __syncthreads();
    #pragma unroll
    for (int off = 1; off < 256; off <<= 1) {
        int x = (t >= off) ? sdata[t - off] : 0;
        __syncthreads();
        sdata[t] += x;
        __syncthreads();
    }
    if (t < NB) d_blksum[t] = sdata[t] - v;
}
__global__ void scan3_kernel(int Nn) {
    int i = blockIdx.x * blockDim.x + threadIdx.x;
    if (i >= Nn) return;
    int val = d_rowptr[i] + d_blksum[i >> 8];
    d_rowptr[i] = val;
    d_cursor[i] = val;
    if (i == Nn - 1) d_rowptr[Nn] = val + d_deg[i];
}
__global__ void scatter_kernel(const int* __restrict__ EI, int Ee) {
    int e = blockIdx.x * blockDim.x + threadIdx.x;
    if (e >= Ee) return;
    int dst = EI[Ee + e];
    int pos = atomicAdd(&d_cursor[dst], 1);
    d_edges[pos] = make_int2(EI[e], e);
}

// ---------------- fused edge kernel: one warp per destination node ----------------
__global__ void __launch_bounds__(256) edgeF_kernel(const float* __restrict__ EA,
                                                    const float* __restrict__ Wcls,
                                                    const float* __restrict__ bcls,
                                                    float* __restrict__ out, int Nn) {
    __shared__ float sWcls[DD * 5];
    __shared__ float sG[8 * DD];
    __shared__ float sW2[2 * DD];
    __shared__ float sBcls[5];
    for (int i = threadIdx.x; i < DD * 5; i += 256) sWcls[i] = Wcls[i];
    for (int i = threadIdx.x; i < 8 * DD; i += 256) sG[i] = d_G8[i];
    for (int i = threadIdx.x; i < 2 * DD; i += 256) sW2[i] = d_W2f[i];
    if (threadIdx.x < 5) sBcls[threadIdx.x] = bcls[threadIdx.x];
    __syncthreads();

    int lane = threadIdx.x & 31;
    int n = blockIdx.x * 8 + (threadIdx.x >> 5);
    if (n >= Nn) return;

    int beg = d_rowptr[n], end = d_rowptr[n + 1];
    const float* rowQ = d_Sf + (size_t)n * SFST;

    float4 q[3], cd[3], acc[3];
    #pragma unroll
    for (int j = 0; j < 3; j++) {
        int ch = lane + 32 * j;
        if (ch < 75) {
            q[j]  = __ldg((const float4*)&rowQ[4 * ch]);
            cd[j] = __ldg((const float4*)&rowQ[304 + 4 * ch]);
        } else {
            q[j] = make_float4(0, 0, 0, 0);
            cd[j] = make_float4(0, 0, 0, 0);
        }
        acc[j] = make_float4(0, 0, 0, 0);
    }
    float den0 = 0, den1 = 0, den2 = 0, den3 = 0;

    for (int p = beg; p < end; p++) {
        int2 se = __ldg(&d_edges[p]);
        int src = se.x, e = se.y;
        const __half* rowS = d_Sh + (size_t)src * SHST;
        float4 ea = __ldg((const float4*)&EA[4 * e]);

        float4 k4[3], cs4[3], v4[3];
        #pragma unroll
        for (int j = 0; j < 3; j++) {
            int ch = lane + 32 * j;
            if (ch < 75) {
                k4[j]  = h4tof4(__ldg((const uint2*)(rowS + 4 * ch)));
                v4[j]  = h4tof4(__ldg((const uint2*)(rowS + 320 + 4 * ch)));
                cs4[j] = h4tof4(__ldg((const uint2*)(rowS + 640 + 4 * ch)));
            } else {
                k4[j] = make_float4(0, 0, 0, 0);
                cs4[j] = make_float4(0, 0, 0, 0);
                v4[j] = make_float4(0, 0, 0, 0);
            }
        }

        float l0 = 0, l1 = 0, l2 = 0, l3 = 0, l4 = 0;
        #pragma unroll
        for (int j = 0; j < 3; j++) {
            int ch = lane + 32 * j;
            if (ch >= 75) continue;
            int c = 4 * ch;
            #pragma unroll
            for (int i = 0; i < 4; i++) {
                int col = c + i;
                float h = fast_tanh((&cd[j].x)[i] + (&cs4[j].x)[i]
                                    + ea.z * sW2[col] + ea.w * sW2[DD + col]);
                const float* wc = sWcls + col * 5;
                l0 = fmaf(h, wc[0], l0); l1 = fmaf(h, wc[1], l1); l2 = fmaf(h, wc[2], l2);
                l3 = fmaf(h, wc[3], l3); l4 = fmaf(h, wc[4], l4);
            }
        }
        #pragma unroll
        for (int o = 16; o; o >>= 1) {
            l0 += __shfl_xor_sync(0xffffffffu, l0, o);
            l1 += __shfl_xor_sync(0xffffffffu, l1, o);
            l2 += __shfl_xor_sync(0xffffffffu, l2, o);
            l3 += __shfl_xor_sync(0xffffffffu, l3, o);
            l4 += __shfl_xor_sync(0xffffffffu, l4, o);
        }
        l0 += sBcls[0]; l1 += sBcls[1]; l2 += sBcls[2]; l3 += sBcls[3]; l4 += sBcls[4];
        float m = fmaxf(fmaxf(fmaxf(l0, l1), fmaxf(l2, l3)), l4);
        float p0 = __expf(l0 - m), p1 = __expf(l1 - m), p2 = __expf(l2 - m);
        float p3 = __expf(l3 - m), p4 = __expf(l4 - m);
        float inv = 1.0f / (p0 + p1 + p2 + p3 + p4);
        p0 *= inv; p1 *= inv; p2 *= inv; p3 *= inv; p4 *= inv;
        float t0 = ea.x > 0.0f ? 1.0f : 0.0f;
        float t1 = ea.y < 0.0f ? 1.0f : 0.0f;

        float4 ef[3];
        float a0 = 0, a1 = 0, a2 = 0, a3 = 0;
        #pragma unroll
        for (int j = 0; j < 3; j++) {
            int ch = lane + 32 * j;
            ef[j] = make_float4(0, 0, 0, 0);
            if (ch >= 75) continue;
            int c = 4 * ch;
            #pragma unroll
            for (int i = 0; i < 4; i++) {
                int col = c + i;
                float efv = sG[2100 + col];
                efv = fmaf(p0, sG[col], efv);
                efv = fmaf(p1, sG[300 + col], efv);
                efv = fmaf(p2, sG[600 + col], efv);
                efv = fmaf(p3, sG[900 + col], efv);
                efv = fmaf(p4, sG[1200 + col], efv);
                efv = fmaf(t0, sG[1500 + col], efv);
                efv = fmaf(t1, sG[1800 + col], efv);
                (&ef[j].x)[i] = efv;
                float pr = (&q[j].x)[i] * ((&k4[j].x)[i] + efv);
                if (col < 75) a0 += pr;
                else if (col < 150) a1 += pr;
                else if (col < 225) a2 += pr;
                else a3 += pr;
            }
        }
        #pragma unroll
        for (int o = 16; o; o >>= 1) {
            a0 += __shfl_xor_sync(0xffffffffu, a0, o);
            a1 += __shfl_xor_sync(0xffffffffu, a1, o);
            a2 += __shfl_xor_sync(0xffffffffu, a2, o);
            a3 += __shfl_xor_sync(0xffffffffu, a3, o);
        }
        const float sc = 0.115470053837925152f;  // 1/sqrt(75)
        float w0 = __expf(a0 * sc), w1 = __expf(a1 * sc);
        float w2 = __expf(a2 * sc), w3 = __expf(a3 * sc);
        den0 += w0; den1 += w1; den2 += w2; den3 += w3;

        #pragma unroll
        for (int j = 0; j < 3; j++) {
            int ch = lane + 32 * j;
            if (ch >= 75) continue;
            int c = 4 * ch;
            #pragma unroll
            for (int i = 0; i < 4; i++) {
                int col = c + i;
                float w = col < 75 ? w0 : (col < 150 ? w1 : (col < 225 ? w2 : w3));
                (&acc[j].x)[i] = fmaf(w, (&v4[j].x)[i] + (&ef[j].x)[i], (&acc[j].x)[i]);
            }
        }
    }

    float i0 = den0 > 0 ? __fdividef(1.0f, den0) : 0.0f;
    float i1 = den1 > 0 ? __fdividef(1.0f, den1) : 0.0f;
    float i2 = den2 > 0 ? __fdividef(1.0f, den2) : 0.0f;
    float i3 = den3 > 0 ? __fdividef(1.0f, den3) : 0.0f;
    #pragma unroll
    for (int j = 0; j < 3; j++) {
        int ch = lane + 32 * j;
        if (ch >= 75) continue;
        int c = 4 * ch;
        float4 o4 = *(float4*)&out[(size_t)n * DD + c];
        #pragma unroll
        for (int i = 0; i < 4; i++) {
            int col = c + i;
            float iv = col < 75 ? i0 : (col < 150 ? i1 : (col < 225 ? i2 : i3));
            (&o4.x)[i] = fmaf((&acc[j].x)[i], iv, (&o4.x)[i]);
        }
        *(float4*)&out[(size_t)n * DD + c] = o4;
    }
}

// ---------------- host launcher ----------------
extern "C" void kernel_launch(void* const* d_in, const int* in_sizes, int n_in,
                              void* d_out, int out_size) {
    const float* x     = (const float*)d_in[0];
    const int*   EI    = (const int*)d_in[1];
    const float* EA    = (const float*)d_in[2];
    const float* nrm   = (const float*)d_in[3];
    const float* Wq    = (const float*)d_in[4];
    const float* bq    = (const float*)d_in[5];
    const float* Wk    = (const float*)d_in[6];
    const float* bk    = (const float*)d_in[7];
    const float* Wv    = (const float*)d_in[8];
    const float* bv    = (const float*)d_in[9];
    const float* We    = (const float*)d_in[10];
    const float* Wn    = (const float*)d_in[11];
    const float* bn    = (const float*)d_in[12];
    const float* Wxy   = (const float*)d_in[13];
    const float* bxy   = (const float*)d_in[14];
    const float* Wloc  = (const float*)d_in[15];
    const float* bloc  = (const float*)d_in[16];
    const float* Wobj  = (const float*)d_in[17];
    const float* bobj  = (const float*)d_in[18];
    const float* Wfus  = (const float*)d_in[19];
    const float* bfus  = (const float*)d_in[20];
    const float* Wcls  = (const float*)d_in[21];
    const float* bcls  = (const float*)d_in[22];
    const float* Wskip = (const float*)d_in[23];
    const float* bskip = (const float*)d_in[24];
    const float* vocab = (const float*)d_in[25];

    int Nn = in_sizes[0] / DD;
    int Ee = in_sizes[1] / 2;
    float* out = (float*)d_out;

    static bool attr_set = false;
    const int gemm_smem = STAGES * (128 * 40 + 128 * 40) * 2;   // 81920 B
    if (!attr_set) {
        cudaFuncSetAttribute(gemm_fp16_kernel, cudaFuncAttributeMaxDynamicSharedMemorySize, gemm_smem);
        attr_set = true;
    }

    fold1_kernel<<<(DD + 127) / 128, 128>>>(Wn, Wxy, Wloc, Wfus, vocab, bxy, bn, bobj, bloc, bfus);
    fold2_kernel<<<(DD + 127) / 128, 128>>>(We);
    buildA_kernel<<<(Nn * 304 + 255) / 256, 256>>>(x, nrm, Nn);
    buildW_kernel<<<(NCOLS * 304 + 255) / 256, 256>>>(Wq, Wk, Wv, Wskip, Wobj, bq, bk, bv, bskip);

    dim3 gg(15, MPAD / 128);  // 15 x 391 (cols 0..1920, cols >= 1800 skipped in epilogue)
    gemm_fp16_kernel<<<gg, 256, gemm_smem>>>(out, Nn);

    int NB = (Nn + 255) / 256;
    zerodeg_kernel<<<NB, 256>>>(Nn);
    hist_kernel<<<(Ee + 255) / 256, 256>>>(EI, Ee);
    scan1_kernel<<<NB, 256>>>(Nn);
    scan2_kernel<<<1, 256>>>(NB);
    scan3_kernel<<<NB, 256>>>(Nn);
    scatter_kernel<<<(Ee + 255) / 256, 256>>>(EI, Ee);

    edgeF_kernel<<<(Nn + 7) / 8, 256>>>(EA, Wcls, bcls, out, Nn);
}